// round 3
// baseline (speedup 1.0000x reference)
#include <cuda_runtime.h>
#include <math.h>

// Problem dims
#define NB   4096
#define DIN  1024
#define DOUT 1024

// Scratch (allocation-free rule: __device__ globals)
__device__ float g_act[(size_t)NB * 2 * DOUT];   // activated [4096, 2048]
__device__ float g_z  [(size_t)NB * DOUT];       // z gate    [4096, 1024]
__device__ float g_hr [(size_t)NB * DOUT];       // h_prev*r  [4096, 1024]

constexpr int BM = 128, BN = 128, BK = 16;

// Generic fused GEMM:  C[M x N] = [A0 | A1] (widths K0, Ktot-K0) @ B (+epilogue)
// B is chosen per-CTA: column-block bn < Nsplit -> Ba (cols bn), else Bb (cols bn-Nsplit).
// MODE 1: spike epilogue   MODE 2: z/r sigmoid  MODE 3: n tanh + blend
template<int MODE>
__global__ __launch_bounds__(256, 2)
void gemm_fused(
    const float* __restrict__ A0, const float* __restrict__ A1, int K0, int Ktot,
    const float* __restrict__ Ba, const float* __restrict__ Bb, int Nsplit, int ldb,
    const float* __restrict__ bias_a, const float* __restrict__ bias_b,
    const float* __restrict__ aux0, const float* __restrict__ aux1,
    const float* __restrict__ aux2,
    float* __restrict__ out_a, float* __restrict__ out_b)
{
    __shared__ float As[2][BK][BM];
    __shared__ float Bs[2][BK][BN];

    const int tid = threadIdx.x;
    const int tx  = tid & 15;
    const int ty  = tid >> 4;
    const int bm  = blockIdx.y * BM;
    const int bn  = blockIdx.x * BN;

    const int sel = (bn >= Nsplit) ? 1 : 0;
    const float* __restrict__ Bp    = sel ? Bb : Ba;
    const float* __restrict__ biasp = sel ? bias_b : bias_a;
    const int bnl = bn - (sel ? Nsplit : 0);

    const int K1 = Ktot - K0;

    // A-tile load mapping: 128 rows x 16 k, float4 along k. 512 float4 / 256 thr.
    const int a_row = tid >> 2;          // 0..63  (second load: +64)
    const int a_k   = (tid & 3) * 4;     // 0,4,8,12
    // B-tile load mapping: 16 k rows x 128 n, float4 along n.
    const int b_k = tid >> 5;            // 0..7   (second load: +8)
    const int b_n = (tid & 31) * 4;

    float4 ra0, ra1, rb0, rb1;

    auto load_g = [&](int kt) {
        const int kbase = kt * BK;
        const float* ap;
        int lda, kb;
        if (kbase < K0) { ap = A0; lda = K0; kb = kbase; }
        else            { ap = A1; lda = K1; kb = kbase - K0; }
        ra0 = *(const float4*)(ap + (size_t)(bm + a_row)      * lda + kb + a_k);
        ra1 = *(const float4*)(ap + (size_t)(bm + a_row + 64) * lda + kb + a_k);
        rb0 = *(const float4*)(Bp + (size_t)(kbase + b_k)     * ldb + bnl + b_n);
        rb1 = *(const float4*)(Bp + (size_t)(kbase + b_k + 8) * ldb + bnl + b_n);
    };
    auto store_s = [&](int buf) {
        As[buf][a_k + 0][a_row] = ra0.x;
        As[buf][a_k + 1][a_row] = ra0.y;
        As[buf][a_k + 2][a_row] = ra0.z;
        As[buf][a_k + 3][a_row] = ra0.w;
        As[buf][a_k + 0][a_row + 64] = ra1.x;
        As[buf][a_k + 1][a_row + 64] = ra1.y;
        As[buf][a_k + 2][a_row + 64] = ra1.z;
        As[buf][a_k + 3][a_row + 64] = ra1.w;
        *(float4*)&Bs[buf][b_k][b_n]     = rb0;
        *(float4*)&Bs[buf][b_k + 8][b_n] = rb1;
    };

    float acc[8][8];
#pragma unroll
    for (int i = 0; i < 8; i++)
#pragma unroll
        for (int j = 0; j < 8; j++) acc[i][j] = 0.f;

    const int KT = Ktot / BK;
    load_g(0);
    store_s(0);
    __syncthreads();

    int buf = 0;
    for (int kt = 0; kt < KT; ++kt) {
        if (kt + 1 < KT) load_g(kt + 1);
#pragma unroll
        for (int k = 0; k < BK; ++k) {
            float4 a0 = *(const float4*)&As[buf][k][ty * 4];
            float4 a1 = *(const float4*)&As[buf][k][ty * 4 + 64];
            float4 b0 = *(const float4*)&Bs[buf][k][tx * 4];
            float4 b1 = *(const float4*)&Bs[buf][k][tx * 4 + 64];
            float av[8] = {a0.x, a0.y, a0.z, a0.w, a1.x, a1.y, a1.z, a1.w};
            float bv[8] = {b0.x, b0.y, b0.z, b0.w, b1.x, b1.y, b1.z, b1.w};
#pragma unroll
            for (int i = 0; i < 8; i++)
#pragma unroll
                for (int j = 0; j < 8; j++)
                    acc[i][j] = fmaf(av[i], bv[j], acc[i][j]);
        }
        if (kt + 1 < KT) store_s(buf ^ 1);
        __syncthreads();
        buf ^= 1;
    }

    // ---- epilogue ----
#pragma unroll
    for (int i = 0; i < 8; i++) {
        const int gm = bm + ((i < 4) ? (ty * 4 + i) : (64 + ty * 4 + i - 4));
#pragma unroll
        for (int j = 0; j < 8; j++) {
            const int nl = bnl + ((j < 4) ? (tx * 4 + j) : (64 + tx * 4 + j - 4));
            if (MODE == 1) {
                // aux0=pot_prev, aux1=tresh, aux2=decay; out_a=activated, out_b=pot_next
                const size_t o = (size_t)gm * (2 * DOUT) + nl;
                float c = acc[i][j] + biasp[nl] + aux0[o];
                bool sp = c > aux1[nl];
                out_a[o] = sp ? c : 0.f;
                out_b[o] = sp ? 0.f : c * aux2[nl];
            } else if (MODE == 2) {
                // aux0=h_prev; sel==0 -> z buffer, sel==1 -> hr buffer
                const size_t o = (size_t)gm * DOUT + nl;
                float v = 1.f / (1.f + expf(-(acc[i][j] + biasp[nl])));
                if (sel == 0) out_a[o] = v;
                else          out_b[o] = aux0[o] * v;
            } else {
                // aux0=z, aux1=h_prev; out_a=h_next
                const size_t o = (size_t)gm * DOUT + nl;
                float nv = tanhf(acc[i][j] + biasp[nl]);
                float z = aux0[o];
                float h = aux1[o];
                out_a[o] = (1.f - z) * h + z * nv;
            }
        }
    }
}

extern "C" void kernel_launch(void* const* d_in, const int* in_sizes, int n_in,
                              void* d_out, int out_size)
{
    const float* x        = (const float*)d_in[0];
    const float* h_prev   = (const float*)d_in[1];
    const float* pot_prev = (const float*)d_in[2];
    const float* W_in     = (const float*)d_in[3];
    const float* b_in     = (const float*)d_in[4];
    const float* tresh    = (const float*)d_in[5];
    const float* decay    = (const float*)d_in[6];
    const float* W_z      = (const float*)d_in[7];
    const float* b_z      = (const float*)d_in[8];
    const float* W_r      = (const float*)d_in[9];
    const float* b_r      = (const float*)d_in[10];
    const float* W_n      = (const float*)d_in[11];
    const float* b_n      = (const float*)d_in[12];

    float* h_out   = (float*)d_out;                      // [4096, 1024]
    float* pot_out = h_out + (size_t)NB * DOUT;          // [4096, 2048]

    float *act, *zbuf, *hrbuf;
    cudaGetSymbolAddress((void**)&act,   g_act);
    cudaGetSymbolAddress((void**)&zbuf,  g_z);
    cudaGetSymbolAddress((void**)&hrbuf, g_hr);

    dim3 blk(256);

    // 1) new_x = [x|h_prev] @ W_in ; spike epilogue -> activated, pot_next
    gemm_fused<1><<<dim3((2 * DOUT) / BN, NB / BM), blk>>>(
        x, h_prev, DIN, DIN + DOUT,
        W_in, W_in, 1 << 30, 2 * DOUT,
        b_in, b_in,
        pot_prev, tresh, decay,
        act, pot_out);

    // 2) [activated|h_prev] @ [W_z , W_r] ; sigmoid -> z, h_prev*r
    gemm_fused<2><<<dim3((2 * DOUT) / BN, NB / BM), blk>>>(
        act, h_prev, 2 * DOUT, 3 * DOUT,
        W_z, W_r, DOUT, DOUT,
        b_z, b_r,
        h_prev, nullptr, nullptr,
        zbuf, hrbuf);

    // 3) n = tanh([activated|h_prev*r] @ W_n) ; h_next = (1-z)h + z n
    gemm_fused<3><<<dim3(DOUT / BN, NB / BM), blk>>>(
        act, hrbuf, 2 * DOUT, 3 * DOUT,
        W_n, W_n, 1 << 30, DOUT,
        b_n, b_n,
        zbuf, h_prev, nullptr,
        h_out, nullptr);
}

// round 5
// speedup vs baseline: 1.7412x; 1.7412x over previous
#include <cuda_runtime.h>
#include <cuda_bf16.h>
#include <math.h>
#include <stdint.h>

typedef __nv_bfloat16 BF;

#define NB   4096
#define DIN  1024
#define DOUT 1024
#define TAU  3e-4f
#define MAXFIX 65536

// ---------------- scratch (__device__ globals; allocation-free rule) ----------------
__device__ BF g_xh [NB * DIN],      g_xl [NB * DIN];
__device__ BF g_hph[NB * DOUT],     g_hpl[NB * DOUT];
__device__ BF g_acth[NB * 2*DOUT],  g_actl[NB * 2*DOUT];
__device__ BF g_hrh[NB * DOUT],     g_hrl[NB * DOUT];
__device__ BF g_w1h [2048*2048],    g_w1l [2048*2048];      // W_in^T  [N=2048][K=2048]
__device__ BF g_wzrh[2048*3072],    g_wzrl[2048*3072];      // [Wz|Wr]^T [N=2048][K=3072]
__device__ BF g_wnh [1024*3072],    g_wnl [1024*3072];      // W_n^T   [N=1024][K=3072]
__device__ float g_z[NB * DOUT];
__device__ int g_fix[MAXFIX];
__device__ int g_cnt;

// ---------------- PTX helpers (arch-generic; no sm_103a-only features) ----------------
__device__ __forceinline__ void cp16(uint32_t s, const void* g) {
    asm volatile("cp.async.cg.shared.global [%0], [%1], 16;" :: "r"(s), "l"(g));
}
__device__ __forceinline__ void cp_commit() { asm volatile("cp.async.commit_group;"); }
template<int N> __device__ __forceinline__ void cp_wait() {
    asm volatile("cp.async.wait_group %0;" :: "n"(N) : "memory");
}
__device__ __forceinline__ void ldsm4(uint32_t* r, uint32_t addr) {
    asm volatile("ldmatrix.sync.aligned.m8n8.x4.shared.b16 {%0,%1,%2,%3}, [%4];"
                 : "=r"(r[0]), "=r"(r[1]), "=r"(r[2]), "=r"(r[3]) : "r"(addr));
}
__device__ __forceinline__ void mma16816(float* d, const uint32_t* a, uint32_t b0, uint32_t b1) {
    asm volatile(
        "mma.sync.aligned.m16n8k16.row.col.f32.bf16.bf16.f32 "
        "{%0,%1,%2,%3}, {%4,%5,%6,%7}, {%8,%9}, {%0,%1,%2,%3};"
        : "+f"(d[0]), "+f"(d[1]), "+f"(d[2]), "+f"(d[3])
        : "r"(a[0]), "r"(a[1]), "r"(a[2]), "r"(a[3]), "r"(b0), "r"(b1));
}
__device__ __forceinline__ void split2(float v, BF& h, BF& l) {
    h = __float2bfloat16(v);
    l = __float2bfloat16(v - __bfloat162float(h));
}

// ---------------- preprocess ----------------
__global__ void zero_cnt_kernel() { g_cnt = 0; }

__global__ void split_rows(const float* __restrict__ in, BF* __restrict__ oh,
                           BF* __restrict__ ol, int n4) {
    for (int i = blockIdx.x * blockDim.x + threadIdx.x; i < n4; i += gridDim.x * blockDim.x) {
        float4 v = ((const float4*)in)[i];
        BF h0, h1, h2, h3, l0, l1, l2, l3;
        split2(v.x, h0, l0); split2(v.y, h1, l1); split2(v.z, h2, l2); split2(v.w, h3, l3);
        __nv_bfloat162* ph = (__nv_bfloat162*)(oh + (size_t)i * 4);
        ph[0] = __halves2bfloat162(h0, h1); ph[1] = __halves2bfloat162(h2, h3);
        __nv_bfloat162* pl = (__nv_bfloat162*)(ol + (size_t)i * 4);
        pl[0] = __halves2bfloat162(l0, l1); pl[1] = __halves2bfloat162(l2, l3);
    }
}

// W [K x N] fp32 -> T_hi/lo rows [n_off + n][k], ldT = K
__global__ void transpose_split(const float* __restrict__ W, int K, int N,
                                BF* __restrict__ Th, BF* __restrict__ Tl,
                                int n_off, int ldT) {
    __shared__ float t[32][33];
    int k0 = blockIdx.y * 32, n0 = blockIdx.x * 32;
    int tx = threadIdx.x, ty = threadIdx.y;
#pragma unroll
    for (int i = 0; i < 32; i += 8)
        t[ty + i][tx] = W[(size_t)(k0 + ty + i) * N + n0 + tx];
    __syncthreads();
#pragma unroll
    for (int i = 0; i < 32; i += 8) {
        float v = t[tx][ty + i];
        BF h, l; split2(v, h, l);
        size_t o = (size_t)(n_off + n0 + ty + i) * ldT + k0 + tx;
        Th[o] = h; Tl[o] = l;
    }
}

// ---------------- HMMA GEMM: BM=128 BN=128 BK=32, bf16x3, fused epilogue ----------------
// smem: per stage, 4 tiles (A_hi, A_lo, B_hi, B_lo), each 128 rows x 80B (64B data + pad)
constexpr uint32_t T_A_LO = 10240, T_B_HI = 20480, T_B_LO = 30720;
constexpr uint32_t STAGE = 40960;
constexpr int SMEM_BYTES = 2 * STAGE;   // 81920

template<int MODE>
__global__ __launch_bounds__(256, 1)
void mma_gemm(const BF* __restrict__ A0h, const BF* __restrict__ A0l, int ldA0, int K0,
              const BF* __restrict__ A1h, const BF* __restrict__ A1l, int ldA1,
              const BF* __restrict__ Bh, const BF* __restrict__ Bl, int Ktot,
              const float* __restrict__ bias, const float* __restrict__ q0,
              const float* __restrict__ q1, const float* __restrict__ q2,
              float* __restrict__ of, BF* __restrict__ oh, BF* __restrict__ ol)
{
    extern __shared__ char smv[];
    const int tid = threadIdx.x, wid = tid >> 5, lane = tid & 31;
    const int bm = blockIdx.y * 128, bn = blockIdx.x * 128;
    const int wm = (wid >> 1) * 32, wn = (wid & 1) * 64;
    const uint32_t sb = (uint32_t)__cvta_generic_to_shared(smv);

    const int r_ld = tid >> 1;           // 0..127
    const int c_ld = (tid & 1) * 2;      // 16B-chunk 0 or 2

    auto issue = [&](int kt) {
        const uint32_t base = sb + (uint32_t)(kt & 1) * STAGE;
        const int kb = kt * 32;
        const BF *ah, *al; int lda, kk;
        if (kb < K0) { ah = A0h; al = A0l; lda = ldA0; kk = kb; }
        else         { ah = A1h; al = A1l; lda = ldA1; kk = kb - K0; }
        const size_t ga = (size_t)(bm + r_ld) * lda + kk + c_ld * 8;
        const size_t gb = (size_t)(bn + r_ld) * Ktot + kb + c_ld * 8;
        const uint32_t so = r_ld * 80u + c_ld * 16u;
        cp16(base + so,               ah + ga); cp16(base + so + 16,               ah + ga + 8);
        cp16(base + T_A_LO + so,      al + ga); cp16(base + T_A_LO + so + 16,      al + ga + 8);
        cp16(base + T_B_HI + so,      Bh + gb); cp16(base + T_B_HI + so + 16,      Bh + gb + 8);
        cp16(base + T_B_LO + so,      Bl + gb); cp16(base + T_B_LO + so + 16,      Bl + gb + 8);
        cp_commit();
    };

    float acc[16][4];
#pragma unroll
    for (int i = 0; i < 16; i++)
#pragma unroll
        for (int j = 0; j < 4; j++) acc[i][j] = 0.f;

    const int KT = Ktot >> 5;
    issue(0);
    for (int kt = 0; kt < KT; ++kt) {
        if (kt + 1 < KT) { issue(kt + 1); cp_wait<1>(); }
        else             { cp_wait<0>(); }
        __syncthreads();
        const uint32_t base = sb + (uint32_t)(kt & 1) * STAGE;
#pragma unroll
        for (int ks = 0; ks < 2; ++ks) {
            uint32_t ahr[2][4], alr[2][4];
#pragma unroll
            for (int i = 0; i < 2; i++) {
                const int row = wm + i * 16 + (lane & 7) + ((lane >> 3) & 1) * 8;
                const uint32_t ad = base + row * 80u + (uint32_t)(ks * 2 + (lane >> 4)) * 16u;
                ldsm4(ahr[i], ad);
                ldsm4(alr[i], ad + T_A_LO);
            }
#pragma unroll
            for (int jj = 0; jj < 4; jj++) {
                const int nrow = wn + jj * 16 + (lane & 7) + (lane >> 4) * 8;
                const uint32_t bd = base + T_B_HI + nrow * 80u +
                                    (uint32_t)(ks * 2 + ((lane >> 3) & 1)) * 16u;
                uint32_t bh[4], bl[4];
                ldsm4(bh, bd);
                ldsm4(bl, bd + (T_B_LO - T_B_HI));
#pragma unroll
                for (int h = 0; h < 2; h++) {
                    const uint32_t b0h = bh[2*h], b1h = bh[2*h+1];
                    const uint32_t b0l = bl[2*h], b1l = bl[2*h+1];
#pragma unroll
                    for (int i = 0; i < 2; i++) {
                        float* d = acc[i * 8 + 2 * jj + h];
                        mma16816(d, ahr[i], b0h, b1h);
                        mma16816(d, ahr[i], b0l, b1l);
                        mma16816(d, alr[i], b0h, b1h);
                    }
                }
            }
        }
        __syncthreads();
    }

    // ---- epilogue (element pairs: n, n+1) ----
#pragma unroll
    for (int i = 0; i < 2; i++) {
#pragma unroll
        for (int nf = 0; nf < 8; nf++) {
#pragma unroll
            for (int hh = 0; hh < 2; hh++) {
                const int m = bm + wm + i * 16 + (lane >> 2) + hh * 8;
                const int n = bn + wn + nf * 8 + (lane & 3) * 2;
                float v0 = acc[i * 8 + nf][hh * 2 + 0];
                float v1 = acc[i * 8 + nf][hh * 2 + 1];
                if (MODE == 1) {
                    const size_t o = (size_t)m * 2048 + n;
                    float c0 = v0 + bias[n]     + q0[o];
                    float c1 = v1 + bias[n + 1] + q0[o + 1];
                    bool s0 = c0 > q1[n], s1 = c1 > q1[n + 1];
                    float2 pv = { s0 ? 0.f : c0 * q2[n], s1 ? 0.f : c1 * q2[n + 1] };
                    *(float2*)(of + o) = pv;
                    float a0 = s0 ? c0 : 0.f, a1 = s1 ? c1 : 0.f;
                    BF h0, l0, h1, l1; split2(a0, h0, l0); split2(a1, h1, l1);
                    *(__nv_bfloat162*)(oh + o) = __halves2bfloat162(h0, h1);
                    *(__nv_bfloat162*)(ol + o) = __halves2bfloat162(l0, l1);
                    if (fabsf(c0 - q1[n]) < TAU) {
                        int ix = atomicAdd(&g_cnt, 1);
                        if (ix < MAXFIX) g_fix[ix] = (int)(m * 2048 + n);
                    }
                    if (fabsf(c1 - q1[n + 1]) < TAU) {
                        int ix = atomicAdd(&g_cnt, 1);
                        if (ix < MAXFIX) g_fix[ix] = (int)(m * 2048 + n + 1);
                    }
                } else if (MODE == 2) {
                    if (n < 1024) {
                        const size_t o = (size_t)m * 1024 + n;
                        float s0 = 1.f / (1.f + expf(-(v0 + bias[n])));
                        float s1 = 1.f / (1.f + expf(-(v1 + bias[n + 1])));
                        *(float2*)(of + o) = make_float2(s0, s1);
                    } else {
                        const int nn = n - 1024;
                        const size_t o = (size_t)m * 1024 + nn;
                        float s0 = 1.f / (1.f + expf(-(v0 + q0[nn])));
                        float s1 = 1.f / (1.f + expf(-(v1 + q0[nn + 1])));
                        float hr0 = q1[o] * s0, hr1 = q1[o + 1] * s1;
                        BF h0, l0, h1, l1; split2(hr0, h0, l0); split2(hr1, h1, l1);
                        *(__nv_bfloat162*)(oh + o) = __halves2bfloat162(h0, h1);
                        *(__nv_bfloat162*)(ol + o) = __halves2bfloat162(l0, l1);
                    }
                } else {
                    const size_t o = (size_t)m * 1024 + n;
                    float t0 = tanhf(v0 + bias[n]);
                    float t1 = tanhf(v1 + bias[n + 1]);
                    float z0 = q0[o], z1 = q0[o + 1];
                    float hp0 = q1[o], hp1 = q1[o + 1];
                    *(float2*)(of + o) = make_float2((1.f - z0) * hp0 + z0 * t0,
                                                     (1.f - z1) * hp1 + z1 * t1);
                }
            }
        }
    }
}

// ---------------- exact (fp64) fixup of near-threshold spikes ----------------
__global__ void fixup(const float* __restrict__ x, const float* __restrict__ h_prev,
                      const float* __restrict__ W_in, const float* __restrict__ b_in,
                      const float* __restrict__ pot_prev, const float* __restrict__ tresh,
                      const float* __restrict__ decay,
                      float* __restrict__ pot_out, BF* __restrict__ act_hi, BF* __restrict__ act_lo)
{
    int w = (blockIdx.x * blockDim.x + threadIdx.x) >> 5;
    int l = threadIdx.x & 31;
    int nw = (gridDim.x * blockDim.x) >> 5;
    int cnt = g_cnt; if (cnt > MAXFIX) cnt = MAXFIX;
    for (; w < cnt; w += nw) {
        int o = g_fix[w];
        int m = o >> 11, n = o & 2047;
        double s = 0.0;
        for (int k = l; k < 2048; k += 32) {
            float a = (k < 1024) ? x[(size_t)m * 1024 + k] : h_prev[(size_t)m * 1024 + k - 1024];
            s += (double)a * (double)W_in[(size_t)k * 2048 + n];
        }
#pragma unroll
        for (int d = 16; d; d >>= 1) s += __shfl_xor_sync(0xFFFFFFFFu, s, d);
        if (l == 0) {
            float cc = (float)s + b_in[n] + pot_prev[(size_t)m * 2048 + n];
            bool sp = cc > tresh[n];
            pot_out[(size_t)m * 2048 + n] = sp ? 0.f : cc * decay[n];
            float a = sp ? cc : 0.f;
            BF hi, lo; split2(a, hi, lo);
            act_hi[(size_t)m * 2048 + n] = hi;
            act_lo[(size_t)m * 2048 + n] = lo;
        }
    }
}

// ---------------- launch ----------------
extern "C" void kernel_launch(void* const* d_in, const int* in_sizes, int n_in,
                              void* d_out, int out_size)
{
    const float* x        = (const float*)d_in[0];
    const float* h_prev   = (const float*)d_in[1];
    const float* pot_prev = (const float*)d_in[2];
    const float* W_in     = (const float*)d_in[3];
    const float* b_in     = (const float*)d_in[4];
    const float* tresh    = (const float*)d_in[5];
    const float* decay    = (const float*)d_in[6];
    const float* W_z      = (const float*)d_in[7];
    const float* b_z      = (const float*)d_in[8];
    const float* W_r      = (const float*)d_in[9];
    const float* b_r      = (const float*)d_in[10];
    const float* W_n      = (const float*)d_in[11];
    const float* b_n      = (const float*)d_in[12];

    float* h_out   = (float*)d_out;                 // [4096,1024]
    float* pot_out = h_out + (size_t)NB * DOUT;     // [4096,2048]

    BF *xh, *xl, *hph, *hpl, *acth, *actl, *hrh, *hrl;
    BF *w1h, *w1l, *wzrh, *wzrl, *wnh, *wnl;
    float* zbuf;
    cudaGetSymbolAddress((void**)&xh, g_xh);     cudaGetSymbolAddress((void**)&xl, g_xl);
    cudaGetSymbolAddress((void**)&hph, g_hph);   cudaGetSymbolAddress((void**)&hpl, g_hpl);
    cudaGetSymbolAddress((void**)&acth, g_acth); cudaGetSymbolAddress((void**)&actl, g_actl);
    cudaGetSymbolAddress((void**)&hrh, g_hrh);   cudaGetSymbolAddress((void**)&hrl, g_hrl);
    cudaGetSymbolAddress((void**)&w1h, g_w1h);   cudaGetSymbolAddress((void**)&w1l, g_w1l);
    cudaGetSymbolAddress((void**)&wzrh, g_wzrh); cudaGetSymbolAddress((void**)&wzrl, g_wzrl);
    cudaGetSymbolAddress((void**)&wnh, g_wnh);   cudaGetSymbolAddress((void**)&wnl, g_wnl);
    cudaGetSymbolAddress((void**)&zbuf, g_z);

    cudaFuncSetAttribute(mma_gemm<1>, cudaFuncAttributeMaxDynamicSharedMemorySize, SMEM_BYTES);
    cudaFuncSetAttribute(mma_gemm<2>, cudaFuncAttributeMaxDynamicSharedMemorySize, SMEM_BYTES);
    cudaFuncSetAttribute(mma_gemm<3>, cudaFuncAttributeMaxDynamicSharedMemorySize, SMEM_BYTES);

    zero_cnt_kernel<<<1, 1>>>();
    split_rows<<<2048, 256>>>(x, xh, xl, NB * DIN / 4);
    split_rows<<<2048, 256>>>(h_prev, hph, hpl, NB * DOUT / 4);
    transpose_split<<<dim3(64, 64), dim3(32, 8)>>>(W_in, 2048, 2048, w1h, w1l, 0, 2048);
    transpose_split<<<dim3(32, 96), dim3(32, 8)>>>(W_z, 3072, 1024, wzrh, wzrl, 0, 3072);
    transpose_split<<<dim3(32, 96), dim3(32, 8)>>>(W_r, 3072, 1024, wzrh, wzrl, 1024, 3072);
    transpose_split<<<dim3(32, 96), dim3(32, 8)>>>(W_n, 3072, 1024, wnh, wnl, 0, 3072);

    // 1) pot_tmp = [x|h_prev]@W_in + b + pot_prev ; spike -> activated(split), pot_next
    mma_gemm<1><<<dim3(16, 32), 256, SMEM_BYTES>>>(
        xh, xl, DIN, DIN, hph, hpl, DOUT,
        w1h, w1l, 2048,
        b_in, pot_prev, tresh, decay,
        pot_out, acth, actl);

    fixup<<<64, 256>>>(x, h_prev, W_in, b_in, pot_prev, tresh, decay, pot_out, acth, actl);

    // 2) [activated|h_prev]@[Wz|Wr] ; sigmoid -> z (fp32), h_prev*r (split)
    mma_gemm<2><<<dim3(16, 32), 256, SMEM_BYTES>>>(
        acth, actl, 2 * DOUT, 2 * DOUT, hph, hpl, DOUT,
        wzrh, wzrl, 3072,
        b_z, b_r, h_prev, nullptr,
        zbuf, hrh, hrl);

    // 3) n = tanh([activated|h*r]@W_n + b_n) ; h_next = (1-z)h + z n
    mma_gemm<3><<<dim3(8, 32), 256, SMEM_BYTES>>>(
        acth, actl, 2 * DOUT, 2 * DOUT, hrh, hrl, DOUT,
        wnh, wnl, 3072,
        b_n, zbuf, h_prev, nullptr,
        h_out, nullptr, nullptr);
}

// round 7
// speedup vs baseline: 2.0678x; 1.1876x over previous
#include <cuda_runtime.h>
#include <cuda_bf16.h>
#include <math.h>
#include <stdint.h>

typedef __nv_bfloat16 BF;

#define NB   4096
#define DIN  1024
#define DOUT 1024
#define TAU  3e-4f
#define MAXFIX 65536

// ---------------- scratch (__device__ globals; allocation-free rule) ----------------
__device__ BF g_xh [NB * DIN],      g_xl [NB * DIN];
__device__ BF g_hph[NB * DOUT],     g_hpl[NB * DOUT];
__device__ BF g_acth[NB * 2*DOUT],  g_actl[NB * 2*DOUT];
__device__ BF g_hrh[NB * DOUT],     g_hrl[NB * DOUT];
__device__ BF g_w1h [2048*2048],    g_w1l [2048*2048];      // W_in^T  [N=2048][K=2048]
__device__ BF g_wzrh[2048*3072],    g_wzrl[2048*3072];      // [Wz|Wr]^T [N=2048][K=3072]
__device__ BF g_wnh [1024*3072],    g_wnl [1024*3072];      // W_n^T   [N=1024][K=3072]
__device__ float g_z[NB * DOUT];
__device__ int g_fix[MAXFIX];
__device__ int g_cnt;

// ---------------- PTX helpers (arch-generic; no sm_103a-only features) ----------------
__device__ __forceinline__ void cp16(uint32_t s, const void* g) {
    asm volatile("cp.async.cg.shared.global [%0], [%1], 16;" :: "r"(s), "l"(g));
}
__device__ __forceinline__ void cp_commit() { asm volatile("cp.async.commit_group;"); }
template<int N> __device__ __forceinline__ void cp_wait() {
    asm volatile("cp.async.wait_group %0;" :: "n"(N) : "memory");
}
__device__ __forceinline__ void ldsm4(uint32_t* r, uint32_t addr) {
    asm volatile("ldmatrix.sync.aligned.m8n8.x4.shared.b16 {%0,%1,%2,%3}, [%4];"
                 : "=r"(r[0]), "=r"(r[1]), "=r"(r[2]), "=r"(r[3]) : "r"(addr));
}
__device__ __forceinline__ void mma16816(float* d, const uint32_t* a, uint32_t b0, uint32_t b1) {
    asm volatile(
        "mma.sync.aligned.m16n8k16.row.col.f32.bf16.bf16.f32 "
        "{%0,%1,%2,%3}, {%4,%5,%6,%7}, {%8,%9}, {%0,%1,%2,%3};"
        : "+f"(d[0]), "+f"(d[1]), "+f"(d[2]), "+f"(d[3])
        : "r"(a[0]), "r"(a[1]), "r"(a[2]), "r"(a[3]), "r"(b0), "r"(b1));
}
__device__ __forceinline__ void split2(float v, BF& h, BF& l) {
    h = __float2bfloat16(v);
    l = __float2bfloat16(v - __bfloat162float(h));
}

// ---------------- preprocess ----------------
__global__ void zero_cnt_kernel() { g_cnt = 0; }

__global__ void split_rows(const float* __restrict__ in, BF* __restrict__ oh,
                           BF* __restrict__ ol, int n4) {
    for (int i = blockIdx.x * blockDim.x + threadIdx.x; i < n4; i += gridDim.x * blockDim.x) {
        float4 v = ((const float4*)in)[i];
        BF h0, h1, h2, h3, l0, l1, l2, l3;
        split2(v.x, h0, l0); split2(v.y, h1, l1); split2(v.z, h2, l2); split2(v.w, h3, l3);
        __nv_bfloat162* ph = (__nv_bfloat162*)(oh + (size_t)i * 4);
        ph[0] = __halves2bfloat162(h0, h1); ph[1] = __halves2bfloat162(h2, h3);
        __nv_bfloat162* pl = (__nv_bfloat162*)(ol + (size_t)i * 4);
        pl[0] = __halves2bfloat162(l0, l1); pl[1] = __halves2bfloat162(l2, l3);
    }
}

// W [K x N] fp32 -> T_hi/lo rows [n_off + n][k], ldT = K
__global__ void transpose_split(const float* __restrict__ W, int K, int N,
                                BF* __restrict__ Th, BF* __restrict__ Tl,
                                int n_off, int ldT) {
    __shared__ float t[32][33];
    int k0 = blockIdx.y * 32, n0 = blockIdx.x * 32;
    int tx = threadIdx.x, ty = threadIdx.y;
#pragma unroll
    for (int i = 0; i < 32; i += 8)
        t[ty + i][tx] = W[(size_t)(k0 + ty + i) * N + n0 + tx];
    __syncthreads();
#pragma unroll
    for (int i = 0; i < 32; i += 8) {
        float v = t[tx][ty + i];
        BF h, l; split2(v, h, l);
        size_t o = (size_t)(n_off + n0 + ty + i) * ldT + k0 + tx;
        Th[o] = h; Tl[o] = l;
    }
}

// ---------------- HMMA GEMM: BM=128 BN=128 BK=32, bf16x3, fused epilogue ----------------
// smem: per stage, 4 tiles (A_hi, A_lo, B_hi, B_lo), each 128 rows x 80B (64B data + pad)
constexpr uint32_t T_A_LO = 10240, T_B_HI = 20480, T_B_LO = 30720;
constexpr uint32_t STAGE = 40960;
constexpr int SMEM_BYTES = 2 * STAGE;   // 81920  (2 CTAs/SM: 160KB of 228KB)

template<int MODE>
__global__ __launch_bounds__(256, 2)
void mma_gemm(const BF* __restrict__ A0h, const BF* __restrict__ A0l, int ldA0, int K0,
              const BF* __restrict__ A1h, const BF* __restrict__ A1l, int ldA1,
              const BF* __restrict__ Bh, const BF* __restrict__ Bl, int Ktot,
              const float* __restrict__ bias, const float* __restrict__ q0,
              const float* __restrict__ q1, const float* __restrict__ q2,
              float* __restrict__ of, BF* __restrict__ oh, BF* __restrict__ ol)
{
    extern __shared__ char smv[];
    const int tid = threadIdx.x, wid = tid >> 5, lane = tid & 31;
    const int bm = blockIdx.y * 128, bn = blockIdx.x * 128;
    const int wm = (wid >> 1) * 32, wn = (wid & 1) * 64;
    const uint32_t sb = (uint32_t)__cvta_generic_to_shared(smv);

    const int r_ld = tid >> 1;           // 0..127
    const int c_ld = (tid & 1) * 2;      // 16B-chunk 0 or 2

    auto issue = [&](int kt) {
        const uint32_t base = sb + (uint32_t)(kt & 1) * STAGE;
        const int kb = kt * 32;
        const BF *ah, *al; int lda, kk;
        if (kb < K0) { ah = A0h; al = A0l; lda = ldA0; kk = kb; }
        else         { ah = A1h; al = A1l; lda = ldA1; kk = kb - K0; }
        const size_t ga = (size_t)(bm + r_ld) * lda + kk + c_ld * 8;
        const size_t gb = (size_t)(bn + r_ld) * Ktot + kb + c_ld * 8;
        const uint32_t so = r_ld * 80u + c_ld * 16u;
        cp16(base + so,               ah + ga); cp16(base + so + 16,               ah + ga + 8);
        cp16(base + T_A_LO + so,      al + ga); cp16(base + T_A_LO + so + 16,      al + ga + 8);
        cp16(base + T_B_HI + so,      Bh + gb); cp16(base + T_B_HI + so + 16,      Bh + gb + 8);
        cp16(base + T_B_LO + so,      Bl + gb); cp16(base + T_B_LO + so + 16,      Bl + gb + 8);
        cp_commit();
    };

    float acc[16][4];
#pragma unroll
    for (int i = 0; i < 16; i++)
#pragma unroll
        for (int j = 0; j < 4; j++) acc[i][j] = 0.f;

    const int KT = Ktot >> 5;
    issue(0);
    for (int kt = 0; kt < KT; ++kt) {
        if (kt + 1 < KT) { issue(kt + 1); cp_wait<1>(); }
        else             { cp_wait<0>(); }
        __syncthreads();
        const uint32_t base = sb + (uint32_t)(kt & 1) * STAGE;
#pragma unroll
        for (int ks = 0; ks < 2; ++ks) {
            uint32_t ahr[2][4], alr[2][4];
#pragma unroll
            for (int i = 0; i < 2; i++) {
                const int row = wm + i * 16 + (lane & 7) + ((lane >> 3) & 1) * 8;
                const uint32_t ad = base + row * 80u + (uint32_t)(ks * 2 + (lane >> 4)) * 16u;
                ldsm4(ahr[i], ad);
                ldsm4(alr[i], ad + T_A_LO);
            }
#pragma unroll
            for (int jj = 0; jj < 4; jj++) {
                const int nrow = wn + jj * 16 + (lane & 7) + (lane >> 4) * 8;
                const uint32_t bd = base + T_B_HI + nrow * 80u +
                                    (uint32_t)(ks * 2 + ((lane >> 3) & 1)) * 16u;
                uint32_t bh[4], bl[4];
                ldsm4(bh, bd);
                ldsm4(bl, bd + (T_B_LO - T_B_HI));
#pragma unroll
                for (int h = 0; h < 2; h++) {
                    const uint32_t b0h = bh[2*h], b1h = bh[2*h+1];
                    const uint32_t b0l = bl[2*h], b1l = bl[2*h+1];
#pragma unroll
                    for (int i = 0; i < 2; i++) {
                        float* d = acc[i * 8 + 2 * jj + h];
                        mma16816(d, ahr[i], b0h, b1h);
                        mma16816(d, ahr[i], b0l, b1l);
                        mma16816(d, alr[i], b0h, b1h);
                    }
                }
            }
        }
        __syncthreads();
    }

    // ---- epilogue (element pairs: n, n+1) ----
#pragma unroll
    for (int i = 0; i < 2; i++) {
#pragma unroll
        for (int nf = 0; nf < 8; nf++) {
#pragma unroll
            for (int hh = 0; hh < 2; hh++) {
                const int m = bm + wm + i * 16 + (lane >> 2) + hh * 8;
                const int n = bn + wn + nf * 8 + (lane & 3) * 2;
                float v0 = acc[i * 8 + nf][hh * 2 + 0];
                float v1 = acc[i * 8 + nf][hh * 2 + 1];
                if (MODE == 1) {
                    const size_t o = (size_t)m * 2048 + n;
                    float c0 = v0 + bias[n]     + q0[o];
                    float c1 = v1 + bias[n + 1] + q0[o + 1];
                    bool s0 = c0 > q1[n], s1 = c1 > q1[n + 1];
                    float2 pv = { s0 ? 0.f : c0 * q2[n], s1 ? 0.f : c1 * q2[n + 1] };
                    *(float2*)(of + o) = pv;
                    float a0 = s0 ? c0 : 0.f, a1 = s1 ? c1 : 0.f;
                    BF h0, l0, h1, l1; split2(a0, h0, l0); split2(a1, h1, l1);
                    *(__nv_bfloat162*)(oh + o) = __halves2bfloat162(h0, h1);
                    *(__nv_bfloat162*)(ol + o) = __halves2bfloat162(l0, l1);
                    if (fabsf(c0 - q1[n]) < TAU) {
                        int ix = atomicAdd(&g_cnt, 1);
                        if (ix < MAXFIX) g_fix[ix] = (int)(m * 2048 + n);
                    }
                    if (fabsf(c1 - q1[n + 1]) < TAU) {
                        int ix = atomicAdd(&g_cnt, 1);
                        if (ix < MAXFIX) g_fix[ix] = (int)(m * 2048 + n + 1);
                    }
                } else if (MODE == 2) {
                    if (n < 1024) {
                        const size_t o = (size_t)m * 1024 + n;
                        float s0 = 1.f / (1.f + expf(-(v0 + bias[n])));
                        float s1 = 1.f / (1.f + expf(-(v1 + bias[n + 1])));
                        *(float2*)(of + o) = make_float2(s0, s1);
                    } else {
                        const int nn = n - 1024;
                        const size_t o = (size_t)m * 1024 + nn;
                        float s0 = 1.f / (1.f + expf(-(v0 + q0[nn])));
                        float s1 = 1.f / (1.f + expf(-(v1 + q0[nn + 1])));
                        float hr0 = q1[o] * s0, hr1 = q1[o + 1] * s1;
                        BF h0, l0, h1, l1; split2(hr0, h0, l0); split2(hr1, h1, l1);
                        *(__nv_bfloat162*)(oh + o) = __halves2bfloat162(h0, h1);
                        *(__nv_bfloat162*)(ol + o) = __halves2bfloat162(l0, l1);
                    }
                } else {
                    const size_t o = (size_t)m * 1024 + n;
                    float t0 = tanhf(v0 + bias[n]);
                    float t1 = tanhf(v1 + bias[n + 1]);
                    float z0 = q0[o], z1 = q0[o + 1];
                    float hp0 = q1[o], hp1 = q1[o + 1];
                    *(float2*)(of + o) = make_float2((1.f - z0) * hp0 + z0 * t0,
                                                     (1.f - z1) * hp1 + z1 * t1);
                }
            }
        }
    }
}

// ---------------- exact (fp64) fixup of near-threshold spikes ----------------
__global__ void fixup(const float* __restrict__ x, const float* __restrict__ h_prev,
                      const float* __restrict__ W_in, const float* __restrict__ b_in,
                      const float* __restrict__ pot_prev, const float* __restrict__ tresh,
                      const float* __restrict__ decay,
                      float* __restrict__ pot_out, BF* __restrict__ act_hi, BF* __restrict__ act_lo)
{
    int w = (blockIdx.x * blockDim.x + threadIdx.x) >> 5;
    int l = threadIdx.x & 31;
    int nw = (gridDim.x * blockDim.x) >> 5;
    int cnt = g_cnt; if (cnt > MAXFIX) cnt = MAXFIX;
    for (; w < cnt; w += nw) {
        int o = g_fix[w];
        int m = o >> 11, n = o & 2047;
        double s = 0.0;
        for (int k = l; k < 2048; k += 32) {
            float a = (k < 1024) ? x[(size_t)m * 1024 + k] : h_prev[(size_t)m * 1024 + k - 1024];
            s += (double)a * (double)W_in[(size_t)k * 2048 + n];
        }
#pragma unroll
        for (int d = 16; d; d >>= 1) s += __shfl_xor_sync(0xFFFFFFFFu, s, d);
        if (l == 0) {
            float cc = (float)s + b_in[n] + pot_prev[(size_t)m * 2048 + n];
            bool sp = cc > tresh[n];
            pot_out[(size_t)m * 2048 + n] = sp ? 0.f : cc * decay[n];
            float a = sp ? cc : 0.f;
            BF hi, lo; split2(a, hi, lo);
            act_hi[(size_t)m * 2048 + n] = hi;
            act_lo[(size_t)m * 2048 + n] = lo;
        }
    }
}

// ---------------- launch ----------------
extern "C" void kernel_launch(void* const* d_in, const int* in_sizes, int n_in,
                              void* d_out, int out_size)
{
    const float* x        = (const float*)d_in[0];
    const float* h_prev   = (const float*)d_in[1];
    const float* pot_prev = (const float*)d_in[2];
    const float* W_in     = (const float*)d_in[3];
    const float* b_in     = (const float*)d_in[4];
    const float* tresh    = (const float*)d_in[5];
    const float* decay    = (const float*)d_in[6];
    const float* W_z      = (const float*)d_in[7];
    const float* b_z      = (const float*)d_in[8];
    const float* W_r      = (const float*)d_in[9];
    const float* b_r      = (const float*)d_in[10];
    const float* W_n      = (const float*)d_in[11];
    const float* b_n      = (const float*)d_in[12];

    float* h_out   = (float*)d_out;                 // [4096,1024]
    float* pot_out = h_out + (size_t)NB * DOUT;     // [4096,2048]

    BF *xh, *xl, *hph, *hpl, *acth, *actl, *hrh, *hrl;
    BF *w1h, *w1l, *wzrh, *wzrl, *wnh, *wnl;
    float* zbuf;
    cudaGetSymbolAddress((void**)&xh, g_xh);     cudaGetSymbolAddress((void**)&xl, g_xl);
    cudaGetSymbolAddress((void**)&hph, g_hph);   cudaGetSymbolAddress((void**)&hpl, g_hpl);
    cudaGetSymbolAddress((void**)&acth, g_acth); cudaGetSymbolAddress((void**)&actl, g_actl);
    cudaGetSymbolAddress((void**)&hrh, g_hrh);   cudaGetSymbolAddress((void**)&hrl, g_hrl);
    cudaGetSymbolAddress((void**)&w1h, g_w1h);   cudaGetSymbolAddress((void**)&w1l, g_w1l);
    cudaGetSymbolAddress((void**)&wzrh, g_wzrh); cudaGetSymbolAddress((void**)&wzrl, g_wzrl);
    cudaGetSymbolAddress((void**)&wnh, g_wnh);   cudaGetSymbolAddress((void**)&wnl, g_wnl);
    cudaGetSymbolAddress((void**)&zbuf, g_z);

    cudaFuncSetAttribute(mma_gemm<1>, cudaFuncAttributeMaxDynamicSharedMemorySize, SMEM_BYTES);
    cudaFuncSetAttribute(mma_gemm<2>, cudaFuncAttributeMaxDynamicSharedMemorySize, SMEM_BYTES);
    cudaFuncSetAttribute(mma_gemm<3>, cudaFuncAttributeMaxDynamicSharedMemorySize, SMEM_BYTES);

    zero_cnt_kernel<<<1, 1>>>();
    split_rows<<<2048, 256>>>(x, xh, xl, NB * DIN / 4);
    split_rows<<<2048, 256>>>(h_prev, hph, hpl, NB * DOUT / 4);
    transpose_split<<<dim3(64, 64), dim3(32, 8)>>>(W_in, 2048, 2048, w1h, w1l, 0, 2048);
    transpose_split<<<dim3(32, 96), dim3(32, 8)>>>(W_z, 3072, 1024, wzrh, wzrl, 0, 3072);
    transpose_split<<<dim3(32, 96), dim3(32, 8)>>>(W_r, 3072, 1024, wzrh, wzrl, 1024, 3072);
    transpose_split<<<dim3(32, 96), dim3(32, 8)>>>(W_n, 3072, 1024, wnh, wnl, 0, 3072);

    // 1) pot_tmp = [x|h_prev]@W_in + b + pot_prev ; spike -> activated(split), pot_next
    mma_gemm<1><<<dim3(16, 32), 256, SMEM_BYTES>>>(
        xh, xl, DIN, DIN, hph, hpl, DOUT,
        w1h, w1l, 2048,
        b_in, pot_prev, tresh, decay,
        pot_out, acth, actl);

    fixup<<<64, 256>>>(x, h_prev, W_in, b_in, pot_prev, tresh, decay, pot_out, acth, actl);

    // 2) [activated|h_prev]@[Wz|Wr] ; sigmoid -> z (fp32), h_prev*r (split)
    mma_gemm<2><<<dim3(16, 32), 256, SMEM_BYTES>>>(
        acth, actl, 2 * DOUT, 2 * DOUT, hph, hpl, DOUT,
        wzrh, wzrl, 3072,
        b_z, b_r, h_prev, nullptr,
        zbuf, hrh, hrl);

    // 3) n = tanh([activated|h*r]@W_n + b_n) ; h_next = (1-z)h + z n
    mma_gemm<3><<<dim3(8, 32), 256, SMEM_BYTES>>>(
        acth, actl, 2 * DOUT, 2 * DOUT, hrh, hrl, DOUT,
        wnh, wnl, 3072,
        b_n, zbuf, h_prev, nullptr,
        h_out, nullptr, nullptr);
}

// round 8
// speedup vs baseline: 2.2090x; 1.0683x over previous
#include <cuda_runtime.h>
#include <cuda_bf16.h>
#include <math.h>
#include <stdint.h>

typedef __nv_bfloat16 BF;

#define NB   4096
#define DIN  1024
#define DOUT 1024
#define TAU  3e-4f
#define MAXFIX 65536

// ---------------- scratch (__device__ globals; allocation-free rule) ----------------
__device__ BF g_xh [NB * DIN],      g_xl [NB * DIN];
__device__ BF g_hph[NB * DOUT],     g_hpl[NB * DOUT];
__device__ BF g_acth[NB * 2*DOUT],  g_actl[NB * 2*DOUT];
__device__ BF g_hrh[NB * DOUT],     g_hrl[NB * DOUT];
__device__ BF g_w1h [2048*2048],    g_w1l [2048*2048];      // W_in^T  [N=2048][K=2048]
__device__ BF g_wzrh[2048*3072],    g_wzrl[2048*3072];      // [Wz|Wr]^T [N=2048][K=3072]
__device__ BF g_wnh [1024*3072],    g_wnl [1024*3072];      // W_n^T   [N=1024][K=3072]
__device__ float g_z[NB * DOUT];
__device__ int g_fix[MAXFIX];
__device__ int g_cnt;

// ---------------- PTX helpers (arch-generic; no sm_103a-only features) ----------------
__device__ __forceinline__ void cp16(uint32_t s, const void* g) {
    asm volatile("cp.async.cg.shared.global [%0], [%1], 16;" :: "r"(s), "l"(g));
}
__device__ __forceinline__ void cp_commit() { asm volatile("cp.async.commit_group;"); }
template<int N> __device__ __forceinline__ void cp_wait() {
    asm volatile("cp.async.wait_group %0;" :: "n"(N) : "memory");
}
__device__ __forceinline__ void ldsm4(uint32_t* r, uint32_t addr) {
    asm volatile("ldmatrix.sync.aligned.m8n8.x4.shared.b16 {%0,%1,%2,%3}, [%4];"
                 : "=r"(r[0]), "=r"(r[1]), "=r"(r[2]), "=r"(r[3]) : "r"(addr));
}
__device__ __forceinline__ void mma16816(float* d, const uint32_t* a, uint32_t b0, uint32_t b1) {
    asm volatile(
        "mma.sync.aligned.m16n8k16.row.col.f32.bf16.bf16.f32 "
        "{%0,%1,%2,%3}, {%4,%5,%6,%7}, {%8,%9}, {%0,%1,%2,%3};"
        : "+f"(d[0]), "+f"(d[1]), "+f"(d[2]), "+f"(d[3])
        : "r"(a[0]), "r"(a[1]), "r"(a[2]), "r"(a[3]), "r"(b0), "r"(b1));
}
__device__ __forceinline__ void split2(float v, BF& h, BF& l) {
    h = __float2bfloat16(v);
    l = __float2bfloat16(v - __bfloat162float(h));
}
// 64B-row tile: chunk swizzle (conflict-free ldmatrix phases)
__device__ __forceinline__ uint32_t tswz(uint32_t row, uint32_t chunk) {
    return row * 64u + ((chunk ^ ((row >> 1) & 3u)) * 16u);
}

// ---------------- preprocess ----------------
__global__ void zero_cnt_kernel() { g_cnt = 0; }

__global__ void split_rows(const float* __restrict__ in, BF* __restrict__ oh,
                           BF* __restrict__ ol, int n4) {
    for (int i = blockIdx.x * blockDim.x + threadIdx.x; i < n4; i += gridDim.x * blockDim.x) {
        float4 v = ((const float4*)in)[i];
        BF h0, h1, h2, h3, l0, l1, l2, l3;
        split2(v.x, h0, l0); split2(v.y, h1, l1); split2(v.z, h2, l2); split2(v.w, h3, l3);
        __nv_bfloat162* ph = (__nv_bfloat162*)(oh + (size_t)i * 4);
        ph[0] = __halves2bfloat162(h0, h1); ph[1] = __halves2bfloat162(h2, h3);
        __nv_bfloat162* pl = (__nv_bfloat162*)(ol + (size_t)i * 4);
        pl[0] = __halves2bfloat162(l0, l1); pl[1] = __halves2bfloat162(l2, l3);
    }
}

// W [K x N] fp32 -> T_hi/lo rows [n_off + n][k], ldT = K
__global__ void transpose_split(const float* __restrict__ W, int K, int N,
                                BF* __restrict__ Th, BF* __restrict__ Tl,
                                int n_off, int ldT) {
    __shared__ float t[32][33];
    int k0 = blockIdx.y * 32, n0 = blockIdx.x * 32;
    int tx = threadIdx.x, ty = threadIdx.y;
#pragma unroll
    for (int i = 0; i < 32; i += 8)
        t[ty + i][tx] = W[(size_t)(k0 + ty + i) * N + n0 + tx];
    __syncthreads();
#pragma unroll
    for (int i = 0; i < 32; i += 8) {
        float v = t[tx][ty + i];
        BF h, l; split2(v, h, l);
        size_t o = (size_t)(n_off + n0 + ty + i) * ldT + k0 + tx;
        Th[o] = h; Tl[o] = l;
    }
}

// ---------------- HMMA GEMM: BM=128 BN=128 BK=32, bf16x3, 3-stage, fused epilogue ----------------
// per stage: 4 tiles (A_hi, A_lo, B_hi, B_lo), each 128 rows x 64B (swizzled) = 8KB
constexpr uint32_t T_A_LO = 8192, T_B_HI = 16384, T_B_LO = 24576;
constexpr uint32_t STAGE = 32768;
constexpr int SMEM_BYTES = 3 * STAGE;   // 98304  (2 CTAs/SM: 192KB of 228KB)

template<int MODE>
__global__ __launch_bounds__(256, 2)
void mma_gemm(const BF* __restrict__ A0h, const BF* __restrict__ A0l, int ldA0, int K0,
              const BF* __restrict__ A1h, const BF* __restrict__ A1l, int ldA1,
              const BF* __restrict__ Bh, const BF* __restrict__ Bl, int Ktot,
              const float* __restrict__ bias, const float* __restrict__ q0,
              const float* __restrict__ q1, const float* __restrict__ q2,
              float* __restrict__ of, BF* __restrict__ oh, BF* __restrict__ ol)
{
    extern __shared__ char smv[];
    const int tid = threadIdx.x, wid = tid >> 5, lane = tid & 31;
    const int bm = blockIdx.y * 128, bn = blockIdx.x * 128;
    const int wm = (wid >> 1) * 32, wn = (wid & 1) * 64;
    const uint32_t sb = (uint32_t)__cvta_generic_to_shared(smv);

    const int r_ld = tid >> 1;           // 0..127
    const int c_ld = (tid & 1) * 2;      // 16B-chunk 0 or 2

    const int KT = Ktot >> 5;

    auto issue = [&](int kt) {
        if (kt >= KT) { cp_commit(); return; }   // empty group keeps wait_group accounting
        const uint32_t base = sb + (uint32_t)(kt % 3) * STAGE;
        const int kb = kt * 32;
        const BF *ah, *al; int lda, kk;
        if (kb < K0) { ah = A0h; al = A0l; lda = ldA0; kk = kb; }
        else         { ah = A1h; al = A1l; lda = ldA1; kk = kb - K0; }
        const size_t ga = (size_t)(bm + r_ld) * lda + kk + c_ld * 8;
        const size_t gb = (size_t)(bn + r_ld) * Ktot + kb + c_ld * 8;
        const uint32_t s0 = tswz(r_ld, c_ld), s1 = tswz(r_ld, c_ld + 1);
        cp16(base + s0,          ah + ga); cp16(base + s1,          ah + ga + 8);
        cp16(base + T_A_LO + s0, al + ga); cp16(base + T_A_LO + s1, al + ga + 8);
        cp16(base + T_B_HI + s0, Bh + gb); cp16(base + T_B_HI + s1, Bh + gb + 8);
        cp16(base + T_B_LO + s0, Bl + gb); cp16(base + T_B_LO + s1, Bl + gb + 8);
        cp_commit();
    };

    float acc[16][4];
#pragma unroll
    for (int i = 0; i < 16; i++)
#pragma unroll
        for (int j = 0; j < 4; j++) acc[i][j] = 0.f;

    issue(0); issue(1);
    for (int kt = 0; kt < KT; ++kt) {
        cp_wait<1>();
        __syncthreads();          // stage kt ready; stage kt-1 fully consumed by all warps
        issue(kt + 2);            // refill stage (kt+2)%3 == (kt-1)%3
        const uint32_t base = sb + (uint32_t)(kt % 3) * STAGE;
#pragma unroll
        for (int ks = 0; ks < 2; ++ks) {
            uint32_t ahr[2][4], alr[2][4];
#pragma unroll
            for (int i = 0; i < 2; i++) {
                const uint32_t row = (uint32_t)(wm + i * 16 + (lane & 7) + ((lane >> 3) & 1) * 8);
                const uint32_t ad = base + tswz(row, (uint32_t)(ks * 2 + (lane >> 4)));
                ldsm4(ahr[i], ad);
                ldsm4(alr[i], ad + T_A_LO);
            }
#pragma unroll
            for (int jj = 0; jj < 4; jj++) {
                const uint32_t nrow = (uint32_t)(wn + jj * 16 + (lane & 7) + (lane >> 4) * 8);
                const uint32_t bd = base + T_B_HI +
                                    tswz(nrow, (uint32_t)(ks * 2 + ((lane >> 3) & 1)));
                uint32_t bh[4], bl[4];
                ldsm4(bh, bd);
                ldsm4(bl, bd + (T_B_LO - T_B_HI));
#pragma unroll
                for (int h = 0; h < 2; h++) {
                    const uint32_t b0h = bh[2*h], b1h = bh[2*h+1];
                    const uint32_t b0l = bl[2*h], b1l = bl[2*h+1];
#pragma unroll
                    for (int i = 0; i < 2; i++) {
                        float* d = acc[i * 8 + 2 * jj + h];
                        mma16816(d, ahr[i], b0h, b1h);
                        mma16816(d, ahr[i], b0l, b1l);
                        mma16816(d, alr[i], b0h, b1h);
                    }
                }
            }
        }
    }
    cp_wait<0>();

    // ---- epilogue (element pairs: n, n+1) ----
#pragma unroll
    for (int i = 0; i < 2; i++) {
#pragma unroll
        for (int nf = 0; nf < 8; nf++) {
#pragma unroll
            for (int hh = 0; hh < 2; hh++) {
                const int m = bm + wm + i * 16 + (lane >> 2) + hh * 8;
                const int n = bn + wn + nf * 8 + (lane & 3) * 2;
                float v0 = acc[i * 8 + nf][hh * 2 + 0];
                float v1 = acc[i * 8 + nf][hh * 2 + 1];
                if (MODE == 1) {
                    const size_t o = (size_t)m * 2048 + n;
                    float c0 = v0 + bias[n]     + q0[o];
                    float c1 = v1 + bias[n + 1] + q0[o + 1];
                    bool s0 = c0 > q1[n], s1 = c1 > q1[n + 1];
                    float2 pv = { s0 ? 0.f : c0 * q2[n], s1 ? 0.f : c1 * q2[n + 1] };
                    *(float2*)(of + o) = pv;
                    float a0 = s0 ? c0 : 0.f, a1 = s1 ? c1 : 0.f;
                    BF h0, l0, h1, l1; split2(a0, h0, l0); split2(a1, h1, l1);
                    *(__nv_bfloat162*)(oh + o) = __halves2bfloat162(h0, h1);
                    *(__nv_bfloat162*)(ol + o) = __halves2bfloat162(l0, l1);
                    if (fabsf(c0 - q1[n]) < TAU) {
                        int ix = atomicAdd(&g_cnt, 1);
                        if (ix < MAXFIX) g_fix[ix] = (int)(m * 2048 + n);
                    }
                    if (fabsf(c1 - q1[n + 1]) < TAU) {
                        int ix = atomicAdd(&g_cnt, 1);
                        if (ix < MAXFIX) g_fix[ix] = (int)(m * 2048 + n + 1);
                    }
                } else if (MODE == 2) {
                    if (n < 1024) {
                        const size_t o = (size_t)m * 1024 + n;
                        float s0 = 1.f / (1.f + expf(-(v0 + bias[n])));
                        float s1 = 1.f / (1.f + expf(-(v1 + bias[n + 1])));
                        *(float2*)(of + o) = make_float2(s0, s1);
                    } else {
                        const int nn = n - 1024;
                        const size_t o = (size_t)m * 1024 + nn;
                        float s0 = 1.f / (1.f + expf(-(v0 + q0[nn])));
                        float s1 = 1.f / (1.f + expf(-(v1 + q0[nn + 1])));
                        float hr0 = q1[o] * s0, hr1 = q1[o + 1] * s1;
                        BF h0, l0, h1, l1; split2(hr0, h0, l0); split2(hr1, h1, l1);
                        *(__nv_bfloat162*)(oh + o) = __halves2bfloat162(h0, h1);
                        *(__nv_bfloat162*)(ol + o) = __halves2bfloat162(l0, l1);
                    }
                } else {
                    const size_t o = (size_t)m * 1024 + n;
                    float t0 = tanhf(v0 + bias[n]);
                    float t1 = tanhf(v1 + bias[n + 1]);
                    float z0 = q0[o], z1 = q0[o + 1];
                    float hp0 = q1[o], hp1 = q1[o + 1];
                    *(float2*)(of + o) = make_float2((1.f - z0) * hp0 + z0 * t0,
                                                     (1.f - z1) * hp1 + z1 * t1);
                }
            }
        }
    }
}

// ---------------- exact (fp64) fixup of near-threshold spikes ----------------
__global__ void fixup(const float* __restrict__ x, const float* __restrict__ h_prev,
                      const float* __restrict__ W_in, const float* __restrict__ b_in,
                      const float* __restrict__ pot_prev, const float* __restrict__ tresh,
                      const float* __restrict__ decay,
                      float* __restrict__ pot_out, BF* __restrict__ act_hi, BF* __restrict__ act_lo)
{
    int w = (blockIdx.x * blockDim.x + threadIdx.x) >> 5;
    int l = threadIdx.x & 31;
    int nw = (gridDim.x * blockDim.x) >> 5;
    int cnt = g_cnt; if (cnt > MAXFIX) cnt = MAXFIX;
    for (; w < cnt; w += nw) {
        int o = g_fix[w];
        int m = o >> 11, n = o & 2047;
        double s = 0.0;
        for (int k = l; k < 2048; k += 32) {
            float a = (k < 1024) ? x[(size_t)m * 1024 + k] : h_prev[(size_t)m * 1024 + k - 1024];
            s += (double)a * (double)W_in[(size_t)k * 2048 + n];
        }
#pragma unroll
        for (int d = 16; d; d >>= 1) s += __shfl_xor_sync(0xFFFFFFFFu, s, d);
        if (l == 0) {
            float cc = (float)s + b_in[n] + pot_prev[(size_t)m * 2048 + n];
            bool sp = cc > tresh[n];
            pot_out[(size_t)m * 2048 + n] = sp ? 0.f : cc * decay[n];
            float a = sp ? cc : 0.f;
            BF hi, lo; split2(a, hi, lo);
            act_hi[(size_t)m * 2048 + n] = hi;
            act_lo[(size_t)m * 2048 + n] = lo;
        }
    }
}

// ---------------- launch ----------------
extern "C" void kernel_launch(void* const* d_in, const int* in_sizes, int n_in,
                              void* d_out, int out_size)
{
    const float* x        = (const float*)d_in[0];
    const float* h_prev   = (const float*)d_in[1];
    const float* pot_prev = (const float*)d_in[2];
    const float* W_in     = (const float*)d_in[3];
    const float* b_in     = (const float*)d_in[4];
    const float* tresh    = (const float*)d_in[5];
    const float* decay    = (const float*)d_in[6];
    const float* W_z      = (const float*)d_in[7];
    const float* b_z      = (const float*)d_in[8];
    const float* W_r      = (const float*)d_in[9];
    const float* b_r      = (const float*)d_in[10];
    const float* W_n      = (const float*)d_in[11];
    const float* b_n      = (const float*)d_in[12];

    float* h_out   = (float*)d_out;                 // [4096,1024]
    float* pot_out = h_out + (size_t)NB * DOUT;     // [4096,2048]

    BF *xh, *xl, *hph, *hpl, *acth, *actl, *hrh, *hrl;
    BF *w1h, *w1l, *wzrh, *wzrl, *wnh, *wnl;
    float* zbuf;
    cudaGetSymbolAddress((void**)&xh, g_xh);     cudaGetSymbolAddress((void**)&xl, g_xl);
    cudaGetSymbolAddress((void**)&hph, g_hph);   cudaGetSymbolAddress((void**)&hpl, g_hpl);
    cudaGetSymbolAddress((void**)&acth, g_acth); cudaGetSymbolAddress((void**)&actl, g_actl);
    cudaGetSymbolAddress((void**)&hrh, g_hrh);   cudaGetSymbolAddress((void**)&hrl, g_hrl);
    cudaGetSymbolAddress((void**)&w1h, g_w1h);   cudaGetSymbolAddress((void**)&w1l, g_w1l);
    cudaGetSymbolAddress((void**)&wzrh, g_wzrh); cudaGetSymbolAddress((void**)&wzrl, g_wzrl);
    cudaGetSymbolAddress((void**)&wnh, g_wnh);   cudaGetSymbolAddress((void**)&wnl, g_wnl);
    cudaGetSymbolAddress((void**)&zbuf, g_z);

    cudaFuncSetAttribute(mma_gemm<1>, cudaFuncAttributeMaxDynamicSharedMemorySize, SMEM_BYTES);
    cudaFuncSetAttribute(mma_gemm<2>, cudaFuncAttributeMaxDynamicSharedMemorySize, SMEM_BYTES);
    cudaFuncSetAttribute(mma_gemm<3>, cudaFuncAttributeMaxDynamicSharedMemorySize, SMEM_BYTES);

    zero_cnt_kernel<<<1, 1>>>();
    split_rows<<<2048, 256>>>(x, xh, xl, NB * DIN / 4);
    split_rows<<<2048, 256>>>(h_prev, hph, hpl, NB * DOUT / 4);
    transpose_split<<<dim3(64, 64), dim3(32, 8)>>>(W_in, 2048, 2048, w1h, w1l, 0, 2048);
    transpose_split<<<dim3(32, 96), dim3(32, 8)>>>(W_z, 3072, 1024, wzrh, wzrl, 0, 3072);
    transpose_split<<<dim3(32, 96), dim3(32, 8)>>>(W_r, 3072, 1024, wzrh, wzrl, 1024, 3072);
    transpose_split<<<dim3(32, 96), dim3(32, 8)>>>(W_n, 3072, 1024, wnh, wnl, 0, 3072);

    // 1) pot_tmp = [x|h_prev]@W_in + b + pot_prev ; spike -> activated(split), pot_next
    mma_gemm<1><<<dim3(16, 32), 256, SMEM_BYTES>>>(
        xh, xl, DIN, DIN, hph, hpl, DOUT,
        w1h, w1l, 2048,
        b_in, pot_prev, tresh, decay,
        pot_out, acth, actl);

    fixup<<<64, 256>>>(x, h_prev, W_in, b_in, pot_prev, tresh, decay, pot_out, acth, actl);

    // 2) [activated|h_prev]@[Wz|Wr] ; sigmoid -> z (fp32), h_prev*r (split)
    mma_gemm<2><<<dim3(16, 32), 256, SMEM_BYTES>>>(
        acth, actl, 2 * DOUT, 2 * DOUT, hph, hpl, DOUT,
        wzrh, wzrl, 3072,
        b_z, b_r, h_prev, nullptr,
        zbuf, hrh, hrl);

    // 3) n = tanh([activated|h*r]@W_n + b_n) ; h_next = (1-z)h + z n
    mma_gemm<3><<<dim3(8, 32), 256, SMEM_BYTES>>>(
        acth, actl, 2 * DOUT, 2 * DOUT, hrh, hrl, DOUT,
        wnh, wnl, 3072,
        b_n, zbuf, h_prev, nullptr,
        h_out, nullptr, nullptr);
}

// round 9
// speedup vs baseline: 2.2164x; 1.0034x over previous
#include <cuda_runtime.h>
#include <cuda_bf16.h>
#include <math.h>
#include <stdint.h>

typedef __nv_bfloat16 BF;

#define NB   4096
#define DIN  1024
#define DOUT 1024
#define TAU  3e-4f
#define MAXFIX 65536

// ---------------- scratch (__device__ globals; allocation-free rule) ----------------
__device__ BF g_xh [NB * DIN],      g_xl [NB * DIN];
__device__ BF g_hph[NB * DOUT],     g_hpl[NB * DOUT];
__device__ BF g_acth[NB * 2*DOUT],  g_actl[NB * 2*DOUT];
__device__ BF g_hrh[NB * DOUT],     g_hrl[NB * DOUT];
__device__ BF g_w1h [2048*2048],    g_w1l [2048*2048];      // W_in^T  [N=2048][K=2048]
__device__ BF g_wzrh[2048*3072],    g_wzrl[2048*3072];      // [Wz|Wr]^T [N=2048][K=3072]
__device__ BF g_wnh [1024*3072],    g_wnl [1024*3072];      // W_n^T   [N=1024][K=3072]
__device__ float g_z[NB * DOUT];
__device__ int g_fix[MAXFIX];
__device__ int g_cnt;

// ---------------- PTX helpers (arch-generic; no sm_103a-only features) ----------------
__device__ __forceinline__ void cp16(uint32_t s, const void* g) {
    asm volatile("cp.async.cg.shared.global [%0], [%1], 16;" :: "r"(s), "l"(g));
}
__device__ __forceinline__ void cp_commit() { asm volatile("cp.async.commit_group;"); }
template<int N> __device__ __forceinline__ void cp_wait() {
    asm volatile("cp.async.wait_group %0;" :: "n"(N) : "memory");
}
__device__ __forceinline__ void ldsm4(uint32_t* r, uint32_t addr) {
    asm volatile("ldmatrix.sync.aligned.m8n8.x4.shared.b16 {%0,%1,%2,%3}, [%4];"
                 : "=r"(r[0]), "=r"(r[1]), "=r"(r[2]), "=r"(r[3]) : "r"(addr));
}
__device__ __forceinline__ void mma16816(float* d, const uint32_t* a, uint32_t b0, uint32_t b1) {
    asm volatile(
        "mma.sync.aligned.m16n8k16.row.col.f32.bf16.bf16.f32 "
        "{%0,%1,%2,%3}, {%4,%5,%6,%7}, {%8,%9}, {%0,%1,%2,%3};"
        : "+f"(d[0]), "+f"(d[1]), "+f"(d[2]), "+f"(d[3])
        : "r"(a[0]), "r"(a[1]), "r"(a[2]), "r"(a[3]), "r"(b0), "r"(b1));
}
__device__ __forceinline__ void split2(float v, BF& h, BF& l) {
    h = __float2bfloat16(v);
    l = __float2bfloat16(v - __bfloat162float(h));
}
// 64B-row tile: chunk swizzle (conflict-free ldmatrix phases)
__device__ __forceinline__ uint32_t tswz(uint32_t row, uint32_t chunk) {
    return row * 64u + ((chunk ^ ((row >> 1) & 3u)) * 16u);
}

// ---------------- preprocess ----------------
__global__ void zero_cnt_kernel() { g_cnt = 0; }

__global__ void split_rows(const float* __restrict__ in, BF* __restrict__ oh,
                           BF* __restrict__ ol, int n4) {
    for (int i = blockIdx.x * blockDim.x + threadIdx.x; i < n4; i += gridDim.x * blockDim.x) {
        float4 v = ((const float4*)in)[i];
        BF h0, h1, h2, h3, l0, l1, l2, l3;
        split2(v.x, h0, l0); split2(v.y, h1, l1); split2(v.z, h2, l2); split2(v.w, h3, l3);
        __nv_bfloat162* ph = (__nv_bfloat162*)(oh + (size_t)i * 4);
        ph[0] = __halves2bfloat162(h0, h1); ph[1] = __halves2bfloat162(h2, h3);
        __nv_bfloat162* pl = (__nv_bfloat162*)(ol + (size_t)i * 4);
        pl[0] = __halves2bfloat162(l0, l1); pl[1] = __halves2bfloat162(l2, l3);
    }
}

// W [K x N] fp32 -> T_hi/lo rows [n_off + n][k], ldT = K
__global__ void transpose_split(const float* __restrict__ W, int K, int N,
                                BF* __restrict__ Th, BF* __restrict__ Tl,
                                int n_off, int ldT) {
    __shared__ float t[32][33];
    int k0 = blockIdx.y * 32, n0 = blockIdx.x * 32;
    int tx = threadIdx.x, ty = threadIdx.y;
#pragma unroll
    for (int i = 0; i < 32; i += 8)
        t[ty + i][tx] = W[(size_t)(k0 + ty + i) * N + n0 + tx];
    __syncthreads();
#pragma unroll
    for (int i = 0; i < 32; i += 8) {
        float v = t[tx][ty + i];
        BF h, l; split2(v, h, l);
        size_t o = (size_t)(n_off + n0 + ty + i) * ldT + k0 + tx;
        Th[o] = h; Tl[o] = l;
    }
}

// ---------------- HMMA GEMM: BM=128 BN=128 BK=32, bf16x3, 3-stage, fused epilogue ----------------
// per stage: 4 tiles (A_hi, A_lo, B_hi, B_lo), each 128 rows x 64B (swizzled) = 8KB
constexpr uint32_t T_A_LO = 8192, T_B_HI = 16384, T_B_LO = 24576;
constexpr uint32_t STAGE = 32768;
constexpr int SMEM_BYTES = 3 * STAGE;   // 98304  (2 CTAs/SM: 192KB of 228KB)

template<int MODE>
__global__ __launch_bounds__(256, 2)
void mma_gemm(const BF* __restrict__ A0h, const BF* __restrict__ A0l, int ldA0, int K0,
              const BF* __restrict__ A1h, const BF* __restrict__ A1l, int ldA1,
              const BF* __restrict__ Bh, const BF* __restrict__ Bl, int Ktot,
              const float* __restrict__ bias, const float* __restrict__ q0,
              const float* __restrict__ q1, const float* __restrict__ q2,
              float* __restrict__ of, BF* __restrict__ oh, BF* __restrict__ ol)
{
    extern __shared__ char smv[];
    const int tid = threadIdx.x, wid = tid >> 5, lane = tid & 31;
    const int bm = blockIdx.y * 128, bn = blockIdx.x * 128;
    const int wm = (wid >> 1) * 32, wn = (wid & 1) * 64;
    const uint32_t sb = (uint32_t)__cvta_generic_to_shared(smv);

    const int r_ld = tid >> 1;           // 0..127
    const int c_ld = (tid & 1) * 2;      // 16B-chunk 0 or 2

    const int KT = Ktot >> 5;

    auto issue = [&](int kt) {
        if (kt >= KT) { cp_commit(); return; }   // empty group keeps wait_group accounting
        const uint32_t base = sb + (uint32_t)(kt % 3) * STAGE;
        const int kb = kt * 32;
        const BF *ah, *al; int lda, kk;
        if (kb < K0) { ah = A0h; al = A0l; lda = ldA0; kk = kb; }
        else         { ah = A1h; al = A1l; lda = ldA1; kk = kb - K0; }
        const size_t ga = (size_t)(bm + r_ld) * lda + kk + c_ld * 8;
        const size_t gb = (size_t)(bn + r_ld) * Ktot + kb + c_ld * 8;
        const uint32_t s0 = tswz(r_ld, c_ld), s1 = tswz(r_ld, c_ld + 1);
        cp16(base + s0,          ah + ga); cp16(base + s1,          ah + ga + 8);
        cp16(base + T_A_LO + s0, al + ga); cp16(base + T_A_LO + s1, al + ga + 8);
        cp16(base + T_B_HI + s0, Bh + gb); cp16(base + T_B_HI + s1, Bh + gb + 8);
        cp16(base + T_B_LO + s0, Bl + gb); cp16(base + T_B_LO + s1, Bl + gb + 8);
        cp_commit();
    };

    float acc[16][4];
#pragma unroll
    for (int i = 0; i < 16; i++)
#pragma unroll
        for (int j = 0; j < 4; j++) acc[i][j] = 0.f;

    issue(0); issue(1);
    for (int kt = 0; kt < KT; ++kt) {
        cp_wait<1>();
        __syncthreads();          // stage kt ready; stage kt-1 fully consumed by all warps
        issue(kt + 2);            // refill stage (kt+2)%3 == (kt-1)%3
        const uint32_t base = sb + (uint32_t)(kt % 3) * STAGE;
#pragma unroll
        for (int ks = 0; ks < 2; ++ks) {
            uint32_t ahr[2][4], alr[2][4];
#pragma unroll
            for (int i = 0; i < 2; i++) {
                const uint32_t row = (uint32_t)(wm + i * 16 + (lane & 7) + ((lane >> 3) & 1) * 8);
                const uint32_t ad = base + tswz(row, (uint32_t)(ks * 2 + (lane >> 4)));
                ldsm4(ahr[i], ad);
                ldsm4(alr[i], ad + T_A_LO);
            }
#pragma unroll
            for (int jj = 0; jj < 4; jj++) {
                const uint32_t nrow = (uint32_t)(wn + jj * 16 + (lane & 7) + (lane >> 4) * 8);
                const uint32_t bd = base + T_B_HI +
                                    tswz(nrow, (uint32_t)(ks * 2 + ((lane >> 3) & 1)));
                uint32_t bh[4], bl[4];
                ldsm4(bh, bd);
                ldsm4(bl, bd + (T_B_LO - T_B_HI));
                // pass-major emission: same-accumulator reuse distance = 4 (covers HMMA latency)
#pragma unroll
                for (int h = 0; h < 2; h++)
#pragma unroll
                    for (int i = 0; i < 2; i++)
                        mma16816(acc[i * 8 + 2 * jj + h], ahr[i], bh[2*h], bh[2*h+1]);
#pragma unroll
                for (int h = 0; h < 2; h++)
#pragma unroll
                    for (int i = 0; i < 2; i++)
                        mma16816(acc[i * 8 + 2 * jj + h], ahr[i], bl[2*h], bl[2*h+1]);
#pragma unroll
                for (int h = 0; h < 2; h++)
#pragma unroll
                    for (int i = 0; i < 2; i++)
                        mma16816(acc[i * 8 + 2 * jj + h], alr[i], bh[2*h], bh[2*h+1]);
            }
        }
    }
    cp_wait<0>();

    // ---- epilogue (element pairs: n, n+1) ----
#pragma unroll
    for (int i = 0; i < 2; i++) {
#pragma unroll
        for (int nf = 0; nf < 8; nf++) {
#pragma unroll
            for (int hh = 0; hh < 2; hh++) {
                const int m = bm + wm + i * 16 + (lane >> 2) + hh * 8;
                const int n = bn + wn + nf * 8 + (lane & 3) * 2;
                float v0 = acc[i * 8 + nf][hh * 2 + 0];
                float v1 = acc[i * 8 + nf][hh * 2 + 1];
                if (MODE == 1) {
                    const size_t o = (size_t)m * 2048 + n;
                    float c0 = v0 + bias[n]     + q0[o];
                    float c1 = v1 + bias[n + 1] + q0[o + 1];
                    bool s0 = c0 > q1[n], s1 = c1 > q1[n + 1];
                    float2 pv = { s0 ? 0.f : c0 * q2[n], s1 ? 0.f : c1 * q2[n + 1] };
                    *(float2*)(of + o) = pv;
                    float a0 = s0 ? c0 : 0.f, a1 = s1 ? c1 : 0.f;
                    BF h0, l0, h1, l1; split2(a0, h0, l0); split2(a1, h1, l1);
                    *(__nv_bfloat162*)(oh + o) = __halves2bfloat162(h0, h1);
                    *(__nv_bfloat162*)(ol + o) = __halves2bfloat162(l0, l1);
                    if (fabsf(c0 - q1[n]) < TAU) {
                        int ix = atomicAdd(&g_cnt, 1);
                        if (ix < MAXFIX) g_fix[ix] = (int)(m * 2048 + n);
                    }
                    if (fabsf(c1 - q1[n + 1]) < TAU) {
                        int ix = atomicAdd(&g_cnt, 1);
                        if (ix < MAXFIX) g_fix[ix] = (int)(m * 2048 + n + 1);
                    }
                } else if (MODE == 2) {
                    if (n < 1024) {
                        const size_t o = (size_t)m * 1024 + n;
                        float s0 = 1.f / (1.f + expf(-(v0 + bias[n])));
                        float s1 = 1.f / (1.f + expf(-(v1 + bias[n + 1])));
                        *(float2*)(of + o) = make_float2(s0, s1);
                    } else {
                        const int nn = n - 1024;
                        const size_t o = (size_t)m * 1024 + nn;
                        float s0 = 1.f / (1.f + expf(-(v0 + q0[nn])));
                        float s1 = 1.f / (1.f + expf(-(v1 + q0[nn + 1])));
                        float hr0 = q1[o] * s0, hr1 = q1[o + 1] * s1;
                        BF h0, l0, h1, l1; split2(hr0, h0, l0); split2(hr1, h1, l1);
                        *(__nv_bfloat162*)(oh + o) = __halves2bfloat162(h0, h1);
                        *(__nv_bfloat162*)(ol + o) = __halves2bfloat162(l0, l1);
                    }
                } else {
                    const size_t o = (size_t)m * 1024 + n;
                    float t0 = tanhf(v0 + bias[n]);
                    float t1 = tanhf(v1 + bias[n + 1]);
                    float z0 = q0[o], z1 = q0[o + 1];
                    float hp0 = q1[o], hp1 = q1[o + 1];
                    *(float2*)(of + o) = make_float2((1.f - z0) * hp0 + z0 * t0,
                                                     (1.f - z1) * hp1 + z1 * t1);
                }
            }
        }
    }
}

// ---------------- exact (fp64) fixup of near-threshold spikes ----------------
__global__ void fixup(const float* __restrict__ x, const float* __restrict__ h_prev,
                      const float* __restrict__ W_in, const float* __restrict__ b_in,
                      const float* __restrict__ pot_prev, const float* __restrict__ tresh,
                      const float* __restrict__ decay,
                      float* __restrict__ pot_out, BF* __restrict__ act_hi, BF* __restrict__ act_lo)
{
    int w = (blockIdx.x * blockDim.x + threadIdx.x) >> 5;
    int l = threadIdx.x & 31;
    int nw = (gridDim.x * blockDim.x) >> 5;
    int cnt = g_cnt; if (cnt > MAXFIX) cnt = MAXFIX;
    for (; w < cnt; w += nw) {
        int o = g_fix[w];
        int m = o >> 11, n = o & 2047;
        double s = 0.0;
        for (int k = l; k < 2048; k += 32) {
            float a = (k < 1024) ? x[(size_t)m * 1024 + k] : h_prev[(size_t)m * 1024 + k - 1024];
            s += (double)a * (double)W_in[(size_t)k * 2048 + n];
        }
#pragma unroll
        for (int d = 16; d; d >>= 1) s += __shfl_xor_sync(0xFFFFFFFFu, s, d);
        if (l == 0) {
            float cc = (float)s + b_in[n] + pot_prev[(size_t)m * 2048 + n];
            bool sp = cc > tresh[n];
            pot_out[(size_t)m * 2048 + n] = sp ? 0.f : cc * decay[n];
            float a = sp ? cc : 0.f;
            BF hi, lo; split2(a, hi, lo);
            act_hi[(size_t)m * 2048 + n] = hi;
            act_lo[(size_t)m * 2048 + n] = lo;
        }
    }
}

// ---------------- launch ----------------
extern "C" void kernel_launch(void* const* d_in, const int* in_sizes, int n_in,
                              void* d_out, int out_size)
{
    const float* x        = (const float*)d_in[0];
    const float* h_prev   = (const float*)d_in[1];
    const float* pot_prev = (const float*)d_in[2];
    const float* W_in     = (const float*)d_in[3];
    const float* b_in     = (const float*)d_in[4];
    const float* tresh    = (const float*)d_in[5];
    const float* decay    = (const float*)d_in[6];
    const float* W_z      = (const float*)d_in[7];
    const float* b_z      = (const float*)d_in[8];
    const float* W_r      = (const float*)d_in[9];
    const float* b_r      = (const float*)d_in[10];
    const float* W_n      = (const float*)d_in[11];
    const float* b_n      = (const float*)d_in[12];

    float* h_out   = (float*)d_out;                 // [4096,1024]
    float* pot_out = h_out + (size_t)NB * DOUT;     // [4096,2048]

    BF *xh, *xl, *hph, *hpl, *acth, *actl, *hrh, *hrl;
    BF *w1h, *w1l, *wzrh, *wzrl, *wnh, *wnl;
    float* zbuf;
    cudaGetSymbolAddress((void**)&xh, g_xh);     cudaGetSymbolAddress((void**)&xl, g_xl);
    cudaGetSymbolAddress((void**)&hph, g_hph);   cudaGetSymbolAddress((void**)&hpl, g_hpl);
    cudaGetSymbolAddress((void**)&acth, g_acth); cudaGetSymbolAddress((void**)&actl, g_actl);
    cudaGetSymbolAddress((void**)&hrh, g_hrh);   cudaGetSymbolAddress((void**)&hrl, g_hrl);
    cudaGetSymbolAddress((void**)&w1h, g_w1h);   cudaGetSymbolAddress((void**)&w1l, g_w1l);
    cudaGetSymbolAddress((void**)&wzrh, g_wzrh); cudaGetSymbolAddress((void**)&wzrl, g_wzrl);
    cudaGetSymbolAddress((void**)&wnh, g_wnh);   cudaGetSymbolAddress((void**)&wnl, g_wnl);
    cudaGetSymbolAddress((void**)&zbuf, g_z);

    cudaFuncSetAttribute(mma_gemm<1>, cudaFuncAttributeMaxDynamicSharedMemorySize, SMEM_BYTES);
    cudaFuncSetAttribute(mma_gemm<2>, cudaFuncAttributeMaxDynamicSharedMemorySize, SMEM_BYTES);
    cudaFuncSetAttribute(mma_gemm<3>, cudaFuncAttributeMaxDynamicSharedMemorySize, SMEM_BYTES);

    // Launch order arranged so graph-launch index 5 (ncu -s 5 -c 1) is gemm1.
    zero_cnt_kernel<<<1, 1>>>();                                                   // 0
    split_rows<<<2048, 256>>>(x, xh, xl, NB * DIN / 4);                            // 1
    split_rows<<<2048, 256>>>(h_prev, hph, hpl, NB * DOUT / 4);                    // 2
    transpose_split<<<dim3(64, 64), dim3(32, 8)>>>(W_in, 2048, 2048, w1h, w1l, 0, 2048);   // 3
    transpose_split<<<dim3(32, 96), dim3(32, 8)>>>(W_z, 3072, 1024, wzrh, wzrl, 0, 3072);  // 4

    // 5) pot_tmp = [x|h_prev]@W_in + b + pot_prev ; spike -> activated(split), pot_next
    mma_gemm<1><<<dim3(16, 32), 256, SMEM_BYTES>>>(
        xh, xl, DIN, DIN, hph, hpl, DOUT,
        w1h, w1l, 2048,
        b_in, pot_prev, tresh, decay,
        pot_out, acth, actl);

    fixup<<<64, 256>>>(x, h_prev, W_in, b_in, pot_prev, tresh, decay, pot_out, acth, actl);  // 6
    transpose_split<<<dim3(32, 96), dim3(32, 8)>>>(W_r, 3072, 1024, wzrh, wzrl, 1024, 3072); // 7
    transpose_split<<<dim3(32, 96), dim3(32, 8)>>>(W_n, 3072, 1024, wnh, wnl, 0, 3072);      // 8

    // 9) [activated|h_prev]@[Wz|Wr] ; sigmoid -> z (fp32), h_prev*r (split)
    mma_gemm<2><<<dim3(16, 32), 256, SMEM_BYTES>>>(
        acth, actl, 2 * DOUT, 2 * DOUT, hph, hpl, DOUT,
        wzrh, wzrl, 3072,
        b_z, b_r, h_prev, nullptr,
        zbuf, hrh, hrl);

    // 10) n = tanh([activated|h*r]@W_n + b_n) ; h_next = (1-z)h + z n
    mma_gemm<3><<<dim3(8, 32), 256, SMEM_BYTES>>>(
        acth, actl, 2 * DOUT, 2 * DOUT, hrh, hrl, DOUT,
        wnh, wnl, 3072,
        b_n, zbuf, h_prev, nullptr,
        h_out, nullptr, nullptr);
}

// round 10
// speedup vs baseline: 2.7411x; 1.2367x over previous
#include <cuda_runtime.h>
#include <cuda_bf16.h>
#include <cuda_fp16.h>
#include <math.h>
#include <stdint.h>

typedef __half HF;

#define NB   4096
#define DIN  1024
#define DOUT 1024
#define TAU  1e-3f
#define MAXFIX 131072

// ---------------- scratch (__device__ globals; allocation-free rule) ----------------
__device__ HF g_xh [NB * DIN],      g_xl [NB * DIN];
__device__ HF g_hph[NB * DOUT],     g_hpl[NB * DOUT];
__device__ HF g_acth[NB * 2*DOUT],  g_actl[NB * 2*DOUT];
__device__ HF g_hrh[NB * DOUT],     g_hrl[NB * DOUT];
__device__ HF g_w1 [2048*2048];       // W_in^T  [N=2048][K=2048] (fp16 truncated)
__device__ HF g_wzr[2048*3072];       // [Wz|Wr]^T [N=2048][K=3072]
__device__ HF g_wn [1024*3072];       // W_n^T   [N=1024][K=3072]
__device__ float g_z[NB * DOUT];
__device__ int g_fix[MAXFIX];
__device__ int g_cnt;

// ---------------- PTX helpers (arch-generic) ----------------
__device__ __forceinline__ void cp16(uint32_t s, const void* g) {
    asm volatile("cp.async.cg.shared.global [%0], [%1], 16;" :: "r"(s), "l"(g));
}
__device__ __forceinline__ void cp_commit() { asm volatile("cp.async.commit_group;"); }
template<int N> __device__ __forceinline__ void cp_wait() {
    asm volatile("cp.async.wait_group %0;" :: "n"(N) : "memory");
}
__device__ __forceinline__ void ldsm4(uint32_t* r, uint32_t addr) {
    asm volatile("ldmatrix.sync.aligned.m8n8.x4.shared.b16 {%0,%1,%2,%3}, [%4];"
                 : "=r"(r[0]), "=r"(r[1]), "=r"(r[2]), "=r"(r[3]) : "r"(addr));
}
__device__ __forceinline__ void mma16816(float* d, const uint32_t* a, uint32_t b0, uint32_t b1) {
    asm volatile(
        "mma.sync.aligned.m16n8k16.row.col.f32.f16.f16.f32 "
        "{%0,%1,%2,%3}, {%4,%5,%6,%7}, {%8,%9}, {%0,%1,%2,%3};"
        : "+f"(d[0]), "+f"(d[1]), "+f"(d[2]), "+f"(d[3])
        : "r"(a[0]), "r"(a[1]), "r"(a[2]), "r"(a[3]), "r"(b0), "r"(b1));
}
__device__ __forceinline__ void split2h(float v, HF& h, HF& l) {
    h = __float2half(v);
    l = __float2half(v - __half2float(h));
}
// 64B-row tile: chunk swizzle (conflict-free ldmatrix phases)
__device__ __forceinline__ uint32_t tswz(uint32_t row, uint32_t chunk) {
    return row * 64u + ((chunk ^ ((row >> 1) & 3u)) * 16u);
}

// ---------------- preprocess ----------------
__global__ void zero_cnt_kernel() { g_cnt = 0; }

__global__ void split_rows(const float* __restrict__ in, HF* __restrict__ oh,
                           HF* __restrict__ ol, int n4) {
    for (int i = blockIdx.x * blockDim.x + threadIdx.x; i < n4; i += gridDim.x * blockDim.x) {
        float4 v = ((const float4*)in)[i];
        HF h0, h1, h2, h3, l0, l1, l2, l3;
        split2h(v.x, h0, l0); split2h(v.y, h1, l1); split2h(v.z, h2, l2); split2h(v.w, h3, l3);
        __half2* ph = (__half2*)(oh + (size_t)i * 4);
        ph[0] = __halves2half2(h0, h1); ph[1] = __halves2half2(h2, h3);
        __half2* pl = (__half2*)(ol + (size_t)i * 4);
        pl[0] = __halves2half2(l0, l1); pl[1] = __halves2half2(l2, l3);
    }
}

// W [K x N] fp32 -> fp16-truncated transpose rows [n_off + n][k], ldT = K
__global__ void transpose_h(const float* __restrict__ W, int K, int N,
                            HF* __restrict__ Th, int n_off, int ldT) {
    __shared__ float t[32][33];
    int k0 = blockIdx.y * 32, n0 = blockIdx.x * 32;
    int tx = threadIdx.x, ty = threadIdx.y;
#pragma unroll
    for (int i = 0; i < 32; i += 8)
        t[ty + i][tx] = W[(size_t)(k0 + ty + i) * N + n0 + tx];
    __syncthreads();
#pragma unroll
    for (int i = 0; i < 32; i += 8) {
        size_t o = (size_t)(n_off + n0 + ty + i) * ldT + k0 + tx;
        Th[o] = __float2half(t[tx][ty + i]);
    }
}

// ---------------- HMMA GEMM: BM=128 BN=128 BK=32, fp16x2 (2-pass), 4-stage ----------------
// per stage: 3 tiles (A_hi, A_lo, B), each 128 rows x 64B (swizzled) = 8KB
constexpr uint32_t T_A_LO = 8192, T_B = 16384;
constexpr uint32_t STAGE = 24576;
constexpr int NSTAGE = 4;
constexpr int SMEM_BYTES = NSTAGE * STAGE;   // 98304  (2 CTAs/SM: 192KB of 228KB)

template<int MODE>
__global__ __launch_bounds__(256, 2)
void mma_gemm(const HF* __restrict__ A0h, const HF* __restrict__ A0l, int ldA0, int K0,
              const HF* __restrict__ A1h, const HF* __restrict__ A1l, int ldA1,
              const HF* __restrict__ Bt, int Ktot,
              const float* __restrict__ bias, const float* __restrict__ q0,
              const float* __restrict__ q1, const float* __restrict__ q2,
              float* __restrict__ of, HF* __restrict__ oh, HF* __restrict__ ol)
{
    extern __shared__ char smv[];
    const int tid = threadIdx.x, wid = tid >> 5, lane = tid & 31;
    const int bm = blockIdx.y * 128, bn = blockIdx.x * 128;
    const int wm = (wid >> 1) * 32, wn = (wid & 1) * 64;
    const uint32_t sb = (uint32_t)__cvta_generic_to_shared(smv);

    const int r_ld = tid >> 1;           // 0..127
    const int c_ld = (tid & 1) * 2;      // 16B-chunk 0 or 2

    const int KT = Ktot >> 5;

    auto issue = [&](int kt) {
        if (kt >= KT) { cp_commit(); return; }   // empty group keeps wait_group accounting
        const uint32_t base = sb + (uint32_t)(kt % NSTAGE) * STAGE;
        const int kb = kt * 32;
        const HF *ah, *al; int lda, kk;
        if (kb < K0) { ah = A0h; al = A0l; lda = ldA0; kk = kb; }
        else         { ah = A1h; al = A1l; lda = ldA1; kk = kb - K0; }
        const size_t ga = (size_t)(bm + r_ld) * lda + kk + c_ld * 8;
        const size_t gb = (size_t)(bn + r_ld) * Ktot + kb + c_ld * 8;
        const uint32_t s0 = tswz(r_ld, c_ld), s1 = tswz(r_ld, c_ld + 1);
        cp16(base + s0,          ah + ga); cp16(base + s1,          ah + ga + 8);
        cp16(base + T_A_LO + s0, al + ga); cp16(base + T_A_LO + s1, al + ga + 8);
        cp16(base + T_B + s0,    Bt + gb); cp16(base + T_B + s1,    Bt + gb + 8);
        cp_commit();
    };

    float acc[16][4];
#pragma unroll
    for (int i = 0; i < 16; i++)
#pragma unroll
        for (int j = 0; j < 4; j++) acc[i][j] = 0.f;

    issue(0); issue(1); issue(2);
    for (int kt = 0; kt < KT; ++kt) {
        cp_wait<2>();
        __syncthreads();          // stage kt ready; stage kt-1 fully consumed by all warps
        issue(kt + 3);            // refill stage (kt+3)%4 == (kt-1)%4
        const uint32_t base = sb + (uint32_t)(kt % NSTAGE) * STAGE;
#pragma unroll
        for (int ks = 0; ks < 2; ++ks) {
            uint32_t ahr[2][4], alr[2][4];
#pragma unroll
            for (int i = 0; i < 2; i++) {
                const uint32_t row = (uint32_t)(wm + i * 16 + (lane & 7) + ((lane >> 3) & 1) * 8);
                const uint32_t ad = base + tswz(row, (uint32_t)(ks * 2 + (lane >> 4)));
                ldsm4(ahr[i], ad);
                ldsm4(alr[i], ad + T_A_LO);
            }
#pragma unroll
            for (int jj = 0; jj < 4; jj++) {
                const uint32_t nrow = (uint32_t)(wn + jj * 16 + (lane & 7) + (lane >> 4) * 8);
                const uint32_t bd = base + T_B +
                                    tswz(nrow, (uint32_t)(ks * 2 + ((lane >> 3) & 1)));
                uint32_t bh[4];
                ldsm4(bh, bd);
#pragma unroll
                for (int h = 0; h < 2; h++)
#pragma unroll
                    for (int i = 0; i < 2; i++)
                        mma16816(acc[i * 8 + 2 * jj + h], ahr[i], bh[2*h], bh[2*h+1]);
#pragma unroll
                for (int h = 0; h < 2; h++)
#pragma unroll
                    for (int i = 0; i < 2; i++)
                        mma16816(acc[i * 8 + 2 * jj + h], alr[i], bh[2*h], bh[2*h+1]);
            }
        }
    }
    cp_wait<0>();

    // ---- epilogue (element pairs: n, n+1) ----
#pragma unroll
    for (int i = 0; i < 2; i++) {
#pragma unroll
        for (int nf = 0; nf < 8; nf++) {
#pragma unroll
            for (int hh = 0; hh < 2; hh++) {
                const int m = bm + wm + i * 16 + (lane >> 2) + hh * 8;
                const int n = bn + wn + nf * 8 + (lane & 3) * 2;
                float v0 = acc[i * 8 + nf][hh * 2 + 0];
                float v1 = acc[i * 8 + nf][hh * 2 + 1];
                if (MODE == 1) {
                    const size_t o = (size_t)m * 2048 + n;
                    float c0 = v0 + bias[n]     + q0[o];
                    float c1 = v1 + bias[n + 1] + q0[o + 1];
                    bool s0 = c0 > q1[n], s1 = c1 > q1[n + 1];
                    float2 pv = { s0 ? 0.f : c0 * q2[n], s1 ? 0.f : c1 * q2[n + 1] };
                    *(float2*)(of + o) = pv;
                    float a0 = s0 ? c0 : 0.f, a1 = s1 ? c1 : 0.f;
                    HF h0, l0, h1, l1; split2h(a0, h0, l0); split2h(a1, h1, l1);
                    *(__half2*)(oh + o) = __halves2half2(h0, h1);
                    *(__half2*)(ol + o) = __halves2half2(l0, l1);
                    if (fabsf(c0 - q1[n]) < TAU) {
                        int ix = atomicAdd(&g_cnt, 1);
                        if (ix < MAXFIX) g_fix[ix] = (int)(m * 2048 + n);
                    }
                    if (fabsf(c1 - q1[n + 1]) < TAU) {
                        int ix = atomicAdd(&g_cnt, 1);
                        if (ix < MAXFIX) g_fix[ix] = (int)(m * 2048 + n + 1);
                    }
                } else if (MODE == 2) {
                    if (n < 1024) {
                        const size_t o = (size_t)m * 1024 + n;
                        float s0 = 1.f / (1.f + expf(-(v0 + bias[n])));
                        float s1 = 1.f / (1.f + expf(-(v1 + bias[n + 1])));
                        *(float2*)(of + o) = make_float2(s0, s1);
                    } else {
                        const int nn = n - 1024;
                        const size_t o = (size_t)m * 1024 + nn;
                        float s0 = 1.f / (1.f + expf(-(v0 + q0[nn])));
                        float s1 = 1.f / (1.f + expf(-(v1 + q0[nn + 1])));
                        float hr0 = q1[o] * s0, hr1 = q1[o + 1] * s1;
                        HF h0, l0, h1, l1; split2h(hr0, h0, l0); split2h(hr1, h1, l1);
                        *(__half2*)(oh + o) = __halves2half2(h0, h1);
                        *(__half2*)(ol + o) = __halves2half2(l0, l1);
                    }
                } else {
                    const size_t o = (size_t)m * 1024 + n;
                    float t0 = tanhf(v0 + bias[n]);
                    float t1 = tanhf(v1 + bias[n + 1]);
                    float z0 = q0[o], z1 = q0[o + 1];
                    float hp0 = q1[o], hp1 = q1[o + 1];
                    *(float2*)(of + o) = make_float2((1.f - z0) * hp0 + z0 * t0,
                                                     (1.f - z1) * hp1 + z1 * t1);
                }
            }
        }
    }
}

// ---------------- exact (fp64) fixup of near-threshold spikes ----------------
__global__ void fixup(const float* __restrict__ x, const float* __restrict__ h_prev,
                      const float* __restrict__ W_in, const float* __restrict__ b_in,
                      const float* __restrict__ pot_prev, const float* __restrict__ tresh,
                      const float* __restrict__ decay,
                      float* __restrict__ pot_out, HF* __restrict__ act_hi, HF* __restrict__ act_lo)
{
    int w = (blockIdx.x * blockDim.x + threadIdx.x) >> 5;
    int l = threadIdx.x & 31;
    int nw = (gridDim.x * blockDim.x) >> 5;
    int cnt = g_cnt; if (cnt > MAXFIX) cnt = MAXFIX;
    for (; w < cnt; w += nw) {
        int o = g_fix[w];
        int m = o >> 11, n = o & 2047;
        double s = 0.0;
        for (int k = l; k < 2048; k += 32) {
            float a = (k < 1024) ? x[(size_t)m * 1024 + k] : h_prev[(size_t)m * 1024 + k - 1024];
            s += (double)a * (double)W_in[(size_t)k * 2048 + n];
        }
#pragma unroll
        for (int d = 16; d; d >>= 1) s += __shfl_xor_sync(0xFFFFFFFFu, s, d);
        if (l == 0) {
            float cc = (float)s + b_in[n] + pot_prev[(size_t)m * 2048 + n];
            bool sp = cc > tresh[n];
            pot_out[(size_t)m * 2048 + n] = sp ? 0.f : cc * decay[n];
            float a = sp ? cc : 0.f;
            HF hi, lo; split2h(a, hi, lo);
            act_hi[(size_t)m * 2048 + n] = hi;
            act_lo[(size_t)m * 2048 + n] = lo;
        }
    }
}

// ---------------- launch ----------------
extern "C" void kernel_launch(void* const* d_in, const int* in_sizes, int n_in,
                              void* d_out, int out_size)
{
    const float* x        = (const float*)d_in[0];
    const float* h_prev   = (const float*)d_in[1];
    const float* pot_prev = (const float*)d_in[2];
    const float* W_in     = (const float*)d_in[3];
    const float* b_in     = (const float*)d_in[4];
    const float* tresh    = (const float*)d_in[5];
    const float* decay    = (const float*)d_in[6];
    const float* W_z      = (const float*)d_in[7];
    const float* b_z      = (const float*)d_in[8];
    const float* W_r      = (const float*)d_in[9];
    const float* b_r      = (const float*)d_in[10];
    const float* W_n      = (const float*)d_in[11];
    const float* b_n      = (const float*)d_in[12];

    float* h_out   = (float*)d_out;                 // [4096,1024]
    float* pot_out = h_out + (size_t)NB * DOUT;     // [4096,2048]

    HF *xh, *xl, *hph, *hpl, *acth, *actl, *hrh, *hrl;
    HF *w1, *wzr, *wn;
    float* zbuf;
    cudaGetSymbolAddress((void**)&xh, g_xh);     cudaGetSymbolAddress((void**)&xl, g_xl);
    cudaGetSymbolAddress((void**)&hph, g_hph);   cudaGetSymbolAddress((void**)&hpl, g_hpl);
    cudaGetSymbolAddress((void**)&acth, g_acth); cudaGetSymbolAddress((void**)&actl, g_actl);
    cudaGetSymbolAddress((void**)&hrh, g_hrh);   cudaGetSymbolAddress((void**)&hrl, g_hrl);
    cudaGetSymbolAddress((void**)&w1, g_w1);
    cudaGetSymbolAddress((void**)&wzr, g_wzr);
    cudaGetSymbolAddress((void**)&wn, g_wn);
    cudaGetSymbolAddress((void**)&zbuf, g_z);

    cudaFuncSetAttribute(mma_gemm<1>, cudaFuncAttributeMaxDynamicSharedMemorySize, SMEM_BYTES);
    cudaFuncSetAttribute(mma_gemm<2>, cudaFuncAttributeMaxDynamicSharedMemorySize, SMEM_BYTES);
    cudaFuncSetAttribute(mma_gemm<3>, cudaFuncAttributeMaxDynamicSharedMemorySize, SMEM_BYTES);

    // Launch order arranged so graph-launch index 5 (ncu -s 5 -c 1) is gemm1.
    zero_cnt_kernel<<<1, 1>>>();                                                   // 0
    split_rows<<<2048, 256>>>(x, xh, xl, NB * DIN / 4);                            // 1
    split_rows<<<2048, 256>>>(h_prev, hph, hpl, NB * DOUT / 4);                    // 2
    transpose_h<<<dim3(64, 64), dim3(32, 8)>>>(W_in, 2048, 2048, w1, 0, 2048);     // 3
    transpose_h<<<dim3(32, 96), dim3(32, 8)>>>(W_z, 3072, 1024, wzr, 0, 3072);     // 4

    // 5) pot_tmp = [x|h_prev]@W_in + b + pot_prev ; spike -> activated(split), pot_next
    mma_gemm<1><<<dim3(16, 32), 256, SMEM_BYTES>>>(
        xh, xl, DIN, DIN, hph, hpl, DOUT,
        w1, 2048,
        b_in, pot_prev, tresh, decay,
        pot_out, acth, actl);

    fixup<<<64, 256>>>(x, h_prev, W_in, b_in, pot_prev, tresh, decay, pot_out, acth, actl);  // 6
    transpose_h<<<dim3(32, 96), dim3(32, 8)>>>(W_r, 3072, 1024, wzr, 1024, 3072);  // 7
    transpose_h<<<dim3(32, 96), dim3(32, 8)>>>(W_n, 3072, 1024, wn, 0, 3072);      // 8

    // 9) [activated|h_prev]@[Wz|Wr] ; sigmoid -> z (fp32), h_prev*r (split)
    mma_gemm<2><<<dim3(16, 32), 256, SMEM_BYTES>>>(
        acth, actl, 2 * DOUT, 2 * DOUT, hph, hpl, DOUT,
        wzr, 3072,
        b_z, b_r, h_prev, nullptr,
        zbuf, hrh, hrl);

    // 10) n = tanh([activated|h*r]@W_n + b_n) ; h_next = (1-z)h + z n
    mma_gemm<3><<<dim3(8, 32), 256, SMEM_BYTES>>>(
        acth, actl, 2 * DOUT, 2 * DOUT, hrh, hrl, DOUT,
        wn, 3072,
        b_n, zbuf, h_prev, nullptr,
        h_out, nullptr, nullptr);
}

// round 14
// speedup vs baseline: 3.4666x; 1.2647x over previous
#include <cuda_runtime.h>
#include <cuda_bf16.h>
#include <cuda_fp16.h>
#include <math.h>
#include <stdint.h>

typedef __half HF;

#define NB   4096
#define DIN  1024
#define DOUT 1024
#define TAU  1e-3f
#define MAXFIX 131072

// ---------------- scratch (__device__ globals; allocation-free rule) ----------------
__device__ HF g_xh [NB * DIN],      g_xl [NB * DIN];
__device__ HF g_hph[NB * DOUT],     g_hpl[NB * DOUT];
__device__ HF g_acth[NB * 2*DOUT];                      // activated (fp16)
__device__ HF g_hrh[NB * DOUT];                         // h_prev*r  (fp16)
__device__ HF g_w1 [2048*2048];       // W_in^T  [N=2048][K=2048] (fp16 truncated)
__device__ HF g_wzr[2048*3072];       // [Wz|Wr]^T [N=2048][K=3072]
__device__ HF g_wn [1024*3072];       // W_n^T   [N=1024][K=3072]
__device__ float g_z[NB * DOUT];
__device__ int g_fix[MAXFIX];
__device__ int g_cnt;

// ---------------- PTX helpers (arch-generic) ----------------
__device__ __forceinline__ void cp16(uint32_t s, const void* g) {
    asm volatile("cp.async.cg.shared.global [%0], [%1], 16;" :: "r"(s), "l"(g));
}
__device__ __forceinline__ void cp_commit() { asm volatile("cp.async.commit_group;"); }
template<int N> __device__ __forceinline__ void cp_wait() {
    asm volatile("cp.async.wait_group %0;" :: "n"(N) : "memory");
}
__device__ __forceinline__ void ldsm4(uint32_t* r, uint32_t addr) {
    asm volatile("ldmatrix.sync.aligned.m8n8.x4.shared.b16 {%0,%1,%2,%3}, [%4];"
                 : "=r"(r[0]), "=r"(r[1]), "=r"(r[2]), "=r"(r[3]) : "r"(addr));
}
__device__ __forceinline__ void mma16816(float* d, const uint32_t* a, uint32_t b0, uint32_t b1) {
    asm volatile(
        "mma.sync.aligned.m16n8k16.row.col.f32.f16.f16.f32 "
        "{%0,%1,%2,%3}, {%4,%5,%6,%7}, {%8,%9}, {%0,%1,%2,%3};"
        : "+f"(d[0]), "+f"(d[1]), "+f"(d[2]), "+f"(d[3])
        : "r"(a[0]), "r"(a[1]), "r"(a[2]), "r"(a[3]), "r"(b0), "r"(b1));
}
__device__ __forceinline__ void split2h(float v, HF& h, HF& l) {
    h = __float2half(v);
    l = __float2half(v - __half2float(h));
}
// 64B-row tile: chunk swizzle (conflict-free ldmatrix phases)
__device__ __forceinline__ uint32_t tswz(uint32_t row, uint32_t chunk) {
    return row * 64u + ((chunk ^ ((row >> 1) & 3u)) * 16u);
}

// ---------------- preprocess ----------------
__global__ void zero_cnt_kernel() { g_cnt = 0; }

__global__ void split_rows(const float* __restrict__ in, HF* __restrict__ oh,
                           HF* __restrict__ ol, int n4) {
    for (int i = blockIdx.x * blockDim.x + threadIdx.x; i < n4; i += gridDim.x * blockDim.x) {
        float4 v = ((const float4*)in)[i];
        HF h0, h1, h2, h3, l0, l1, l2, l3;
        split2h(v.x, h0, l0); split2h(v.y, h1, l1); split2h(v.z, h2, l2); split2h(v.w, h3, l3);
        __half2* ph = (__half2*)(oh + (size_t)i * 4);
        ph[0] = __halves2half2(h0, h1); ph[1] = __halves2half2(h2, h3);
        __half2* pl = (__half2*)(ol + (size_t)i * 4);
        pl[0] = __halves2half2(l0, l1); pl[1] = __halves2half2(l2, l3);
    }
}

// W [K x N] fp32 -> fp16-truncated transpose rows [n_off + n][k], ldT = K
__global__ void transpose_h(const float* __restrict__ W, int K, int N,
                            HF* __restrict__ Th, int n_off, int ldT) {
    __shared__ float t[32][33];
    int k0 = blockIdx.y * 32, n0 = blockIdx.x * 32;
    int tx = threadIdx.x, ty = threadIdx.y;
#pragma unroll
    for (int i = 0; i < 32; i += 8)
        t[ty + i][tx] = W[(size_t)(k0 + ty + i) * N + n0 + tx];
    __syncthreads();
#pragma unroll
    for (int i = 0; i < 32; i += 8) {
        size_t o = (size_t)(n_off + n0 + ty + i) * ldT + k0 + tx;
        Th[o] = __float2half(t[tx][ty + i]);
    }
}

// ---------------- HMMA GEMM: BM=128 BN=128 BK=32, PASSES in {1,2}, 4-stage ----------------
// per stage: PASSES+1 tiles (A_hi[, A_lo], B), each 128 rows x 64B (swizzled) = 8KB
template<int PASSES> struct Cfg {
    static constexpr uint32_t T_A_LO = 8192;                     // (2-pass only)
    static constexpr uint32_t T_B    = PASSES == 2 ? 16384 : 8192;
    static constexpr uint32_t STAGE  = (PASSES + 1) * 8192u;
    static constexpr int      NSTAGE = 4;
    static constexpr int      SMEM   = NSTAGE * (int)STAGE;      // 96KB / 64KB
};

template<int MODE, int PASSES>
__global__ __launch_bounds__(256, 2)
void mma_gemm(const HF* __restrict__ A0h, const HF* __restrict__ A0l, int ldA0, int K0,
              const HF* __restrict__ A1h, const HF* __restrict__ A1l, int ldA1,
              const HF* __restrict__ Bt, int Ktot,
              const float* __restrict__ bias, const float* __restrict__ q0,
              const float* __restrict__ q1, const float* __restrict__ q2,
              float* __restrict__ of, HF* __restrict__ oh, HF* __restrict__ ol)
{
    using C = Cfg<PASSES>;
    extern __shared__ char smv[];
    const int tid = threadIdx.x, wid = tid >> 5, lane = tid & 31;
    const int bm = blockIdx.y * 128, bn = blockIdx.x * 128;
    const int wm = (wid >> 1) * 32, wn = (wid & 1) * 64;
    const uint32_t sb = (uint32_t)__cvta_generic_to_shared(smv);

    const int r_ld = tid >> 1;           // 0..127
    const int c_ld = (tid & 1) * 2;      // 16B-chunk 0 or 2

    const int KT = Ktot >> 5;

    auto issue = [&](int kt) {
        if (kt >= KT) { cp_commit(); return; }   // empty group keeps wait_group accounting
        const uint32_t base = sb + (uint32_t)(kt % C::NSTAGE) * C::STAGE;
        const int kb = kt * 32;
        const HF *ah, *al; int lda, kk;
        if (kb < K0) { ah = A0h; al = A0l; lda = ldA0; kk = kb; }
        else         { ah = A1h; al = A1l; lda = ldA1; kk = kb - K0; }
        const size_t ga = (size_t)(bm + r_ld) * lda + kk + c_ld * 8;
        const size_t gb = (size_t)(bn + r_ld) * Ktot + kb + c_ld * 8;
        const uint32_t s0 = tswz(r_ld, c_ld), s1 = tswz(r_ld, c_ld + 1);
        cp16(base + s0, ah + ga); cp16(base + s1, ah + ga + 8);
        if (PASSES == 2) {
            cp16(base + C::T_A_LO + s0, al + ga); cp16(base + C::T_A_LO + s1, al + ga + 8);
        }
        cp16(base + C::T_B + s0, Bt + gb); cp16(base + C::T_B + s1, Bt + gb + 8);
        cp_commit();
    };

    float acc[16][4];
#pragma unroll
    for (int i = 0; i < 16; i++)
#pragma unroll
        for (int j = 0; j < 4; j++) acc[i][j] = 0.f;

    issue(0); issue(1); issue(2);
    for (int kt = 0; kt < KT; ++kt) {
        cp_wait<2>();
        __syncthreads();          // stage kt ready; stage kt-1 fully consumed by all warps
        issue(kt + 3);            // refill stage (kt+3)%4 == (kt-1)%4
        const uint32_t base = sb + (uint32_t)(kt % C::NSTAGE) * C::STAGE;
#pragma unroll
        for (int ks = 0; ks < 2; ++ks) {
            uint32_t ahr[2][4], alr[2][4];
#pragma unroll
            for (int i = 0; i < 2; i++) {
                const uint32_t row = (uint32_t)(wm + i * 16 + (lane & 7) + ((lane >> 3) & 1) * 8);
                const uint32_t ad = base + tswz(row, (uint32_t)(ks * 2 + (lane >> 4)));
                ldsm4(ahr[i], ad);
                if (PASSES == 2) ldsm4(alr[i], ad + C::T_A_LO);
            }
#pragma unroll
            for (int jj = 0; jj < 4; jj++) {
                const uint32_t nrow = (uint32_t)(wn + jj * 16 + (lane & 7) + (lane >> 4) * 8);
                const uint32_t bd = base + C::T_B +
                                    tswz(nrow, (uint32_t)(ks * 2 + ((lane >> 3) & 1)));
                uint32_t bh[4];
                ldsm4(bh, bd);
#pragma unroll
                for (int h = 0; h < 2; h++)
#pragma unroll
                    for (int i = 0; i < 2; i++)
                        mma16816(acc[i * 8 + 2 * jj + h], ahr[i], bh[2*h], bh[2*h+1]);
                if (PASSES == 2) {
#pragma unroll
                    for (int h = 0; h < 2; h++)
#pragma unroll
                        for (int i = 0; i < 2; i++)
                            mma16816(acc[i * 8 + 2 * jj + h], alr[i], bh[2*h], bh[2*h+1]);
                }
            }
        }
    }
    cp_wait<0>();

    // ---- epilogue (element pairs: n, n+1) ----
#pragma unroll
    for (int i = 0; i < 2; i++) {
#pragma unroll
        for (int nf = 0; nf < 8; nf++) {
#pragma unroll
            for (int hh = 0; hh < 2; hh++) {
                const int m = bm + wm + i * 16 + (lane >> 2) + hh * 8;
                const int n = bn + wn + nf * 8 + (lane & 3) * 2;
                float v0 = acc[i * 8 + nf][hh * 2 + 0];
                float v1 = acc[i * 8 + nf][hh * 2 + 1];
                if (MODE == 1) {
                    const size_t o = (size_t)m * 2048 + n;
                    float c0 = v0 + bias[n]     + q0[o];
                    float c1 = v1 + bias[n + 1] + q0[o + 1];
                    bool s0 = c0 > q1[n], s1 = c1 > q1[n + 1];
                    float2 pv = { s0 ? 0.f : c0 * q2[n], s1 ? 0.f : c1 * q2[n + 1] };
                    *(float2*)(of + o) = pv;
                    float a0 = s0 ? c0 : 0.f, a1 = s1 ? c1 : 0.f;
                    *(__half2*)(oh + o) = __halves2half2(__float2half(a0), __float2half(a1));
                    if (fabsf(c0 - q1[n]) < TAU) {
                        int ix = atomicAdd(&g_cnt, 1);
                        if (ix < MAXFIX) g_fix[ix] = (int)(m * 2048 + n);
                    }
                    if (fabsf(c1 - q1[n + 1]) < TAU) {
                        int ix = atomicAdd(&g_cnt, 1);
                        if (ix < MAXFIX) g_fix[ix] = (int)(m * 2048 + n + 1);
                    }
                } else if (MODE == 2) {
                    if (n < 1024) {
                        const size_t o = (size_t)m * 1024 + n;
                        float s0 = 1.f / (1.f + expf(-(v0 + bias[n])));
                        float s1 = 1.f / (1.f + expf(-(v1 + bias[n + 1])));
                        *(float2*)(of + o) = make_float2(s0, s1);
                    } else {
                        const int nn = n - 1024;
                        const size_t o = (size_t)m * 1024 + nn;
                        float s0 = 1.f / (1.f + expf(-(v0 + q0[nn])));
                        float s1 = 1.f / (1.f + expf(-(v1 + q0[nn + 1])));
                        float hr0 = q1[o] * s0, hr1 = q1[o + 1] * s1;
                        *(__half2*)(oh + o) = __halves2half2(__float2half(hr0), __float2half(hr1));
                    }
                } else {
                    const size_t o = (size_t)m * 1024 + n;
                    float t0 = tanhf(v0 + bias[n]);
                    float t1 = tanhf(v1 + bias[n + 1]);
                    float z0 = q0[o], z1 = q0[o + 1];
                    float hp0 = q1[o], hp1 = q1[o + 1];
                    *(float2*)(of + o) = make_float2((1.f - z0) * hp0 + z0 * t0,
                                                     (1.f - z1) * hp1 + z1 * t1);
                }
            }
        }
    }
}

// ---------------- exact (fp64) fixup of near-threshold spikes ----------------
__global__ void fixup(const float* __restrict__ x, const float* __restrict__ h_prev,
                      const float* __restrict__ W_in, const float* __restrict__ b_in,
                      const float* __restrict__ pot_prev, const float* __restrict__ tresh,
                      const float* __restrict__ decay,
                      float* __restrict__ pot_out, HF* __restrict__ act_hi)
{
    int w = (blockIdx.x * blockDim.x + threadIdx.x) >> 5;
    int l = threadIdx.x & 31;
    int nw = (gridDim.x * blockDim.x) >> 5;
    int cnt = g_cnt; if (cnt > MAXFIX) cnt = MAXFIX;
    for (; w < cnt; w += nw) {
        int o = g_fix[w];
        int m = o >> 11, n = o & 2047;
        double s = 0.0;
        for (int k = l; k < 2048; k += 32) {
            float a = (k < 1024) ? x[(size_t)m * 1024 + k] : h_prev[(size_t)m * 1024 + k - 1024];
            s += (double)a * (double)W_in[(size_t)k * 2048 + n];
        }
#pragma unroll
        for (int d = 16; d; d >>= 1) s += __shfl_xor_sync(0xFFFFFFFFu, s, d);
        if (l == 0) {
            float cc = (float)s + b_in[n] + pot_prev[(size_t)m * 2048 + n];
            bool sp = cc > tresh[n];
            pot_out[(size_t)m * 2048 + n] = sp ? 0.f : cc * decay[n];
            act_hi[(size_t)m * 2048 + n] = __float2half(sp ? cc : 0.f);
        }
    }
}

// ---------------- launch ----------------
extern "C" void kernel_launch(void* const* d_in, const int* in_sizes, int n_in,
                              void* d_out, int out_size)
{
    const float* x        = (const float*)d_in[0];
    const float* h_prev   = (const float*)d_in[1];
    const float* pot_prev = (const float*)d_in[2];
    const float* W_in     = (const float*)d_in[3];
    const float* b_in     = (const float*)d_in[4];
    const float* tresh    = (const float*)d_in[5];
    const float* decay    = (const float*)d_in[6];
    const float* W_z      = (const float*)d_in[7];
    const float* b_z      = (const float*)d_in[8];
    const float* W_r      = (const float*)d_in[9];
    const float* b_r      = (const float*)d_in[10];
    const float* W_n      = (const float*)d_in[11];
    const float* b_n      = (const float*)d_in[12];

    float* h_out   = (float*)d_out;                 // [4096,1024]
    float* pot_out = h_out + (size_t)NB * DOUT;     // [4096,2048]

    HF *xh, *xl, *hph, *hpl, *acth, *hrh;
    HF *w1, *wzr, *wn;
    float* zbuf;
    cudaGetSymbolAddress((void**)&xh, g_xh);     cudaGetSymbolAddress((void**)&xl, g_xl);
    cudaGetSymbolAddress((void**)&hph, g_hph);   cudaGetSymbolAddress((void**)&hpl, g_hpl);
    cudaGetSymbolAddress((void**)&acth, g_acth);
    cudaGetSymbolAddress((void**)&hrh, g_hrh);
    cudaGetSymbolAddress((void**)&w1, g_w1);
    cudaGetSymbolAddress((void**)&wzr, g_wzr);
    cudaGetSymbolAddress((void**)&wn, g_wn);
    cudaGetSymbolAddress((void**)&zbuf, g_z);

    cudaFuncSetAttribute(mma_gemm<1,2>, cudaFuncAttributeMaxDynamicSharedMemorySize, Cfg<2>::SMEM);
    cudaFuncSetAttribute(mma_gemm<2,1>, cudaFuncAttributeMaxDynamicSharedMemorySize, Cfg<1>::SMEM);
    cudaFuncSetAttribute(mma_gemm<3,1>, cudaFuncAttributeMaxDynamicSharedMemorySize, Cfg<1>::SMEM);

    // Launch order arranged so graph-launch index 5 (ncu -s 5 -c 1) is gemm1.
    zero_cnt_kernel<<<1, 1>>>();                                                   // 0
    split_rows<<<2048, 256>>>(x, xh, xl, NB * DIN / 4);                            // 1
    split_rows<<<2048, 256>>>(h_prev, hph, hpl, NB * DOUT / 4);                    // 2
    transpose_h<<<dim3(64, 64), dim3(32, 8)>>>(W_in, 2048, 2048, w1, 0, 2048);     // 3
    transpose_h<<<dim3(32, 96), dim3(32, 8)>>>(W_z, 3072, 1024, wzr, 0, 3072);     // 4

    // 5) pot_tmp = [x|h_prev]@W_in + b + pot_prev ; spike -> activated, pot_next  (2-pass)
    mma_gemm<1,2><<<dim3(16, 32), 256, Cfg<2>::SMEM>>>(
        xh, xl, DIN, DIN, hph, hpl, DOUT,
        w1, 2048,
        b_in, pot_prev, tresh, decay,
        pot_out, acth, nullptr);

    fixup<<<64, 256>>>(x, h_prev, W_in, b_in, pot_prev, tresh, decay, pot_out, acth);  // 6
    transpose_h<<<dim3(32, 96), dim3(32, 8)>>>(W_r, 3072, 1024, wzr, 1024, 3072);  // 7
    transpose_h<<<dim3(32, 96), dim3(32, 8)>>>(W_n, 3072, 1024, wn, 0, 3072);      // 8

    // 9) [activated|h_prev]@[Wz|Wr] ; sigmoid -> z (fp32), h_prev*r (fp16)  (1-pass)
    mma_gemm<2,1><<<dim3(16, 32), 256, Cfg<1>::SMEM>>>(
        acth, nullptr, 2 * DOUT, 2 * DOUT, hph, nullptr, DOUT,
        wzr, 3072,
        b_z, b_r, h_prev, nullptr,
        zbuf, hrh, nullptr);

    // 10) n = tanh([activated|h*r]@W_n + b_n) ; h_next = (1-z)h + z n  (1-pass)
    mma_gemm<3,1><<<dim3(8, 32), 256, Cfg<1>::SMEM>>>(
        acth, nullptr, 2 * DOUT, 2 * DOUT, hrh, nullptr, DOUT,
        wn, 3072,
        b_n, zbuf, h_prev, nullptr,
        h_out, nullptr, nullptr);
}